// round 1
// baseline (speedup 1.0000x reference)
#include <cuda_runtime.h>
#include <math.h>

// Problem constants
#define BSZ 16
#define NN_ 1024
#define DD_ 128
#define HH_ 8

// ---------------------------------------------------------------------------
// Static scratch (no allocation allowed)
// ---------------------------------------------------------------------------
__device__ float g_c   [BSZ * NN_ * DD_];          // 8 MB   c = F_c + t_emb
__device__ float g_q   [BSZ * NN_ * HH_ * DD_];    // 64 MB  [b, n, h*128+d]
__device__ float g_k   [BSZ * NN_ * HH_ * DD_];    // 64 MB
__device__ float g_v   [BSZ * NN_ * HH_ * DD_];    // 64 MB
__device__ float g_s   [HH_ * NN_ * NN_];          // 32 MB  per-batch scores scratch
__device__ float g_ctx [BSZ * NN_ * HH_ * DD_];    // 64 MB  [b, n, h*128+d]
__device__ float g_h   [BSZ * NN_ * DD_];          // 8 MB
__device__ float g_hw  [BSZ * NN_ * DD_];          // 8 MB
__device__ float g_feat[BSZ * NN_ * DD_];          // 8 MB
__device__ float g_norm[BSZ * NN_ * DD_];          // 8 MB

// ---------------------------------------------------------------------------
// c = F_c + timestep_emb(t)[:, :, None]
// grid: BSZ*NN_ blocks, 128 threads (one per d)
// ---------------------------------------------------------------------------
__global__ void k_embed_add(const float* __restrict__ F_c,
                            const int*   __restrict__ t,
                            float*       __restrict__ c) {
    int bn = blockIdx.x;
    int b  = bn >> 10;
    int n  = bn & 1023;
    float tv = (float)t[b];
    const float kC = logf(1000.0f) / 511.0f;   // log(MAX_T)/(half-1)
    int   i = (n < 512) ? n : (n - 512);
    float f = __expf(-(float)i * kC);
    float e = tv * f;
    float emb = (n < 512) ? sinf(e) : cosf(e);
    size_t base = (size_t)bn * DD_;
    int d = threadIdx.x;
    c[base + d] = F_c[base + d] + emb;
}

// ---------------------------------------------------------------------------
// Generic tiled fp32 GEMM, C = alpha * A@B (+bias) (+relu)
// A: [M,K] row-major lda ; B: [K,N] row-major ldb ; C: [M,N] row-major ldc
// blockDim = 256, tile 64x64x16, 4x4 per thread. M,N mult of 64; K mult of 16.
// grid.z batches with element strides sA/sB/sC.
// ---------------------------------------------------------------------------
template<bool RELU, bool HASBIAS>
__global__ void __launch_bounds__(256)
gemm_nn(const float* __restrict__ A, int lda, size_t sA,
        const float* __restrict__ B, int ldb, size_t sB,
        float*       __restrict__ C, int ldc, size_t sC,
        const float* __restrict__ bias,
        int M, int N, int K, float alpha) {
    __shared__ float As[16][64];
    __shared__ float Bs[16][64];
    A += (size_t)blockIdx.z * sA;
    B += (size_t)blockIdx.z * sB;
    C += (size_t)blockIdx.z * sC;
    int m0 = blockIdx.y * 64, n0 = blockIdx.x * 64;
    int tid = threadIdx.x;
    int tx = tid & 15, ty = tid >> 4;
    int aRow = tid >> 2, aK4 = (tid & 3) << 2;
    int bRow = tid >> 4, bN4 = (tid & 15) << 2;

    float acc[4][4] = {};
    for (int k0 = 0; k0 < K; k0 += 16) {
        float4 av = *(const float4*)(A + (size_t)(m0 + aRow) * lda + k0 + aK4);
        As[aK4 + 0][aRow] = av.x;
        As[aK4 + 1][aRow] = av.y;
        As[aK4 + 2][aRow] = av.z;
        As[aK4 + 3][aRow] = av.w;
        float4 bv = *(const float4*)(B + (size_t)(k0 + bRow) * ldb + n0 + bN4);
        *(float4*)&Bs[bRow][bN4] = bv;
        __syncthreads();
        #pragma unroll
        for (int k = 0; k < 16; k++) {
            float4 a4 = *(const float4*)&As[k][ty << 2];
            float4 b4 = *(const float4*)&Bs[k][tx << 2];
            float ar[4] = {a4.x, a4.y, a4.z, a4.w};
            float br[4] = {b4.x, b4.y, b4.z, b4.w};
            #pragma unroll
            for (int i = 0; i < 4; i++)
                #pragma unroll
                for (int j = 0; j < 4; j++)
                    acc[i][j] = fmaf(ar[i], br[j], acc[i][j]);
        }
        __syncthreads();
    }
    #pragma unroll
    for (int i = 0; i < 4; i++) {
        int row = m0 + (ty << 2) + i;
        #pragma unroll
        for (int j = 0; j < 4; j++) {
            int col = n0 + (tx << 2) + j;
            float v = acc[i][j] * alpha;
            if (HASBIAS) v += bias[col];
            if (RELU)    v = fmaxf(v, 0.0f);
            C[(size_t)row * ldc + col] = v;
        }
    }
}

// C = alpha * A @ B^T ; A: [M,K] lda ; B: [N,K] ldb ; C: [M,N] ldc
__global__ void __launch_bounds__(256)
gemm_nt(const float* __restrict__ A, int lda, size_t sA,
        const float* __restrict__ B, int ldb, size_t sB,
        float*       __restrict__ C, int ldc, size_t sC,
        int M, int N, int K, float alpha) {
    __shared__ float As[16][64];
    __shared__ float Bs[16][64];
    A += (size_t)blockIdx.z * sA;
    B += (size_t)blockIdx.z * sB;
    C += (size_t)blockIdx.z * sC;
    int m0 = blockIdx.y * 64, n0 = blockIdx.x * 64;
    int tid = threadIdx.x;
    int tx = tid & 15, ty = tid >> 4;
    int aRow = tid >> 2, aK4 = (tid & 3) << 2;

    float acc[4][4] = {};
    for (int k0 = 0; k0 < K; k0 += 16) {
        float4 av = *(const float4*)(A + (size_t)(m0 + aRow) * lda + k0 + aK4);
        As[aK4 + 0][aRow] = av.x;
        As[aK4 + 1][aRow] = av.y;
        As[aK4 + 2][aRow] = av.z;
        As[aK4 + 3][aRow] = av.w;
        float4 bv = *(const float4*)(B + (size_t)(n0 + aRow) * ldb + k0 + aK4);
        Bs[aK4 + 0][aRow] = bv.x;
        Bs[aK4 + 1][aRow] = bv.y;
        Bs[aK4 + 2][aRow] = bv.z;
        Bs[aK4 + 3][aRow] = bv.w;
        __syncthreads();
        #pragma unroll
        for (int k = 0; k < 16; k++) {
            float4 a4 = *(const float4*)&As[k][ty << 2];
            float4 b4 = *(const float4*)&Bs[k][tx << 2];
            float ar[4] = {a4.x, a4.y, a4.z, a4.w};
            float br[4] = {b4.x, b4.y, b4.z, b4.w};
            #pragma unroll
            for (int i = 0; i < 4; i++)
                #pragma unroll
                for (int j = 0; j < 4; j++)
                    acc[i][j] = fmaf(ar[i], br[j], acc[i][j]);
        }
        __syncthreads();
    }
    #pragma unroll
    for (int i = 0; i < 4; i++) {
        int row = m0 + (ty << 2) + i;
        #pragma unroll
        for (int j = 0; j < 4; j++) {
            int col = n0 + (tx << 2) + j;
            C[(size_t)row * ldc + col] = acc[i][j] * alpha;
        }
    }
}

// ---------------------------------------------------------------------------
// Row softmax over 1024 columns; one block (256 threads) per row.
// ---------------------------------------------------------------------------
__global__ void k_softmax(float* __restrict__ S) {
    float* row = S + (size_t)blockIdx.x * 1024;
    int tid = threadIdx.x;
    float vals[4];
    float lmax = -INFINITY;
    #pragma unroll
    for (int i = 0; i < 4; i++) {
        vals[i] = row[tid + i * 256];
        lmax = fmaxf(lmax, vals[i]);
    }
    __shared__ float red[256];
    red[tid] = lmax;
    __syncthreads();
    for (int s = 128; s > 0; s >>= 1) {
        if (tid < s) red[tid] = fmaxf(red[tid], red[tid + s]);
        __syncthreads();
    }
    float m = red[0];
    __syncthreads();
    float lsum = 0.0f;
    #pragma unroll
    for (int i = 0; i < 4; i++) {
        vals[i] = __expf(vals[i] - m);
        lsum += vals[i];
    }
    red[tid] = lsum;
    __syncthreads();
    for (int s = 128; s > 0; s >>= 1) {
        if (tid < s) red[tid] += red[tid + s];
        __syncthreads();
    }
    float inv = 1.0f / red[0];
    #pragma unroll
    for (int i = 0; i < 4; i++) row[tid + i * 256] = vals[i] * inv;
}

// ---------------------------------------------------------------------------
// Row normalize: (x - mean) / (std_ddof1 + 1e-8). One block (128 thr) per row.
// ---------------------------------------------------------------------------
__global__ void k_rownorm(const float* __restrict__ feat,
                          float*       __restrict__ out) {
    int tid = threadIdx.x;
    size_t base = (size_t)blockIdx.x * DD_;
    float x = feat[base + tid];
    __shared__ float red[4];
    float s = x;
    #pragma unroll
    for (int o = 16; o > 0; o >>= 1) s += __shfl_xor_sync(0xffffffffu, s, o);
    if ((tid & 31) == 0) red[tid >> 5] = s;
    __syncthreads();
    float mu = (red[0] + red[1] + red[2] + red[3]) * (1.0f / 128.0f);
    float d = x - mu;
    float ss = d * d;
    #pragma unroll
    for (int o = 16; o > 0; o >>= 1) ss += __shfl_xor_sync(0xffffffffu, ss, o);
    __syncthreads();
    if ((tid & 31) == 0) red[tid >> 5] = ss;
    __syncthreads();
    float var = (red[0] + red[1] + red[2] + red[3]) * (1.0f / 127.0f);
    float inv = 1.0f / (sqrtf(var) + 1e-8f);
    out[base + tid] = d * inv;
}

// ---------------------------------------------------------------------------
extern "C" void kernel_launch(void* const* d_in, const int* in_sizes, int n_in,
                              void* d_out, int out_size) {
    const float* A_t = (const float*)d_in[0];
    const float* F_c = (const float*)d_in[1];
    const int*   t   = (const int*)  d_in[2];
    const float* Wq  = (const float*)d_in[3];
    const float* bq  = (const float*)d_in[4];
    const float* Wk  = (const float*)d_in[5];
    const float* bk  = (const float*)d_in[6];
    const float* Wv  = (const float*)d_in[7];
    const float* bv  = (const float*)d_in[8];
    const float* Wo  = (const float*)d_in[9];
    const float* bo  = (const float*)d_in[10];
    const float* Wg  = (const float*)d_in[11];
    float* out = (float*)d_out;

    float *c, *q, *k, *v, *s, *ctx, *h, *hw, *feat, *nrm;
    cudaGetSymbolAddress((void**)&c,    g_c);
    cudaGetSymbolAddress((void**)&q,    g_q);
    cudaGetSymbolAddress((void**)&k,    g_k);
    cudaGetSymbolAddress((void**)&v,    g_v);
    cudaGetSymbolAddress((void**)&s,    g_s);
    cudaGetSymbolAddress((void**)&ctx,  g_ctx);
    cudaGetSymbolAddress((void**)&h,    g_h);
    cudaGetSymbolAddress((void**)&hw,   g_hw);
    cudaGetSymbolAddress((void**)&feat, g_feat);
    cudaGetSymbolAddress((void**)&nrm,  g_norm);

    const size_t sBN  = (size_t)NN_ * HH_ * DD_;   // 1M elems per batch (q/k/v/ctx)
    const size_t sBD  = (size_t)NN_ * DD_;         // 128K elems per batch
    const size_t sHNN = (size_t)NN_ * NN_;         // per-head scores
    const float  scl  = 0.08838834764831845f;      // 1/sqrt(128)

    // 1) c = F_c + t_emb
    k_embed_add<<<BSZ * NN_, DD_>>>(F_c, t, c);

    // 2) QKV projections: per batch, [1024,128] @ [128,1024] + bias
    {
        dim3 g(16, 16, BSZ);
        gemm_nn<false, true><<<g, 256>>>(c, DD_, sBD, Wq, HH_ * DD_, 0,
                                         q, HH_ * DD_, sBN, bq,
                                         NN_, HH_ * DD_, DD_, 1.0f);
        gemm_nn<false, true><<<g, 256>>>(c, DD_, sBD, Wk, HH_ * DD_, 0,
                                         k, HH_ * DD_, sBN, bk,
                                         NN_, HH_ * DD_, DD_, 1.0f);
        gemm_nn<false, true><<<g, 256>>>(c, DD_, sBD, Wv, HH_ * DD_, 0,
                                         v, HH_ * DD_, sBN, bv,
                                         NN_, HH_ * DD_, DD_, 1.0f);
    }

    // 3) Attention per batch (scores scratch reused; stream ordering serializes)
    for (int b = 0; b < BSZ; b++) {
        const float* qb = q + (size_t)b * sBN;
        const float* kb = k + (size_t)b * sBN;
        const float* vb = v + (size_t)b * sBN;
        float*       cb = ctx + (size_t)b * sBN;
        // scores[h] = scl * Q_h @ K_h^T   (head offset = h*128, lda/ldb = 1024)
        dim3 gs(16, 16, HH_);
        gemm_nt<<<gs, 256>>>(qb, HH_ * DD_, DD_, kb, HH_ * DD_, DD_,
                             s, NN_, sHNN, NN_, NN_, DD_, scl);
        // softmax rows
        k_softmax<<<HH_ * NN_, 256>>>(s);
        // ctx[h] = P_h @ V_h  -> stored [n, h*128+d]
        dim3 gc(2, 16, HH_);
        gemm_nn<false, false><<<gc, 256>>>(s, NN_, sHNN, vb, HH_ * DD_, DD_,
                                           cb, HH_ * DD_, DD_, nullptr,
                                           NN_, DD_, NN_, 1.0f);
    }

    // 4) h = ctx @ Wo + bo   [1024,1024] @ [1024,128]
    {
        dim3 g(2, 16, BSZ);
        gemm_nn<false, true><<<g, 256>>>(ctx, HH_ * DD_, sBN, Wo, DD_, 0,
                                         h, DD_, sBD, bo,
                                         NN_, DD_, HH_ * DD_, 1.0f);
    }
    // 5) hw = h @ Wg   [1024,128] @ [128,128]
    {
        dim3 g(2, 16, BSZ);
        gemm_nn<false, false><<<g, 256>>>(h, DD_, sBD, Wg, DD_, 0,
                                          hw, DD_, sBD, nullptr,
                                          NN_, DD_, DD_, 1.0f);
    }
    // 6) feat = relu(A_t @ hw)   [1024,1024] @ [1024,128]
    {
        dim3 g(2, 16, BSZ);
        gemm_nn<true, false><<<g, 256>>>(A_t, NN_, sHNN * 0 + (size_t)NN_ * NN_,
                                         hw, DD_, sBD,
                                         feat, DD_, sBD, nullptr,
                                         NN_, DD_, NN_, 1.0f);
    }
    // 7) row normalize (mean, ddof=1 std)
    k_rownorm<<<BSZ * NN_, DD_>>>(feat, nrm);

    // 8) out = (norm @ norm^T) / 128
    {
        dim3 g(16, 16, BSZ);
        gemm_nt<<<g, 256>>>(nrm, DD_, sBD, nrm, DD_, sBD,
                            out, NN_, (size_t)NN_ * NN_,
                            NN_, NN_, DD_, 1.0f / 128.0f);
    }
}

// round 2
// speedup vs baseline: 1.6980x; 1.6980x over previous
#include <cuda_runtime.h>
#include <math.h>

#define BSZ 16
#define NN_ 1024
#define DD_ 128
#define HH_ 8
#define PAD 132   // 16-row smem tiles padded to 132 floats/row (float4-aligned, low conflict)

// ---------------------------------------------------------------------------
// Static scratch (no allocation allowed)
// ---------------------------------------------------------------------------
__device__ float g_c   [BSZ * NN_ * DD_];             // 8 MB
__device__ float g_q   [BSZ * NN_ * HH_ * DD_];       // 64 MB  [b, n, h*128+d]
__device__ float g_k   [BSZ * NN_ * HH_ * DD_];       // 64 MB
__device__ float g_v   [BSZ * NN_ * HH_ * DD_];       // 64 MB
__device__ float g_s   [134217728];                   // 512 MB [b, h, n, m]
__device__ float g_ctx [BSZ * NN_ * HH_ * DD_];       // 64 MB  [b, n, h*128+d]
__device__ float g_h   [BSZ * NN_ * DD_];
__device__ float g_hw  [BSZ * NN_ * DD_];
__device__ float g_feat[BSZ * NN_ * DD_];
__device__ float g_norm[BSZ * NN_ * DD_];

// ---------------------------------------------------------------------------
// c = F_c + timestep_emb(t)[:, :, None]
// ---------------------------------------------------------------------------
__global__ void k_embed_add(const float* __restrict__ F_c,
                            const int*   __restrict__ t,
                            float*       __restrict__ c) {
    int bn = blockIdx.x;
    int b  = bn >> 10;
    int n  = bn & 1023;
    float tv = (float)t[b];
    const float kC = logf(1000.0f) / 511.0f;
    int   i = (n < 512) ? n : (n - 512);
    float f = __expf(-(float)i * kC);
    float e = tv * f;
    float emb = (n < 512) ? sinf(e) : cosf(e);
    size_t base = (size_t)bn * DD_;
    int d = threadIdx.x;
    c[base + d] = F_c[base + d] + emb;
}

// ---------------------------------------------------------------------------
// 128x128x16 fp32 GEMM, 256 threads, 8x8/thread, double-buffered.
// C = alpha * A @ B(^T) (+bias) (+relu)
// A [M,K] row-major. B: TRANSB ? [N,K] : [K,N] row-major. C [M,N] row-major.
// Batch offsets: z = blockIdx.z; zo = z / zInner, zi = z % zInner;
//   ptr += zo*Out + zi*In   (per-operand).
// Requires: M,N multiples of 128; K multiple of 16.
// ---------------------------------------------------------------------------
template<bool RELU, bool HASBIAS, bool TRANSB>
__global__ void __launch_bounds__(256, 2)
gemm128(const float* __restrict__ A, int lda, size_t aOut, size_t aIn,
        const float* __restrict__ B, int ldb, size_t bOut, size_t bIn,
        float*       __restrict__ C, int ldc, size_t cOut, size_t cIn,
        const float* __restrict__ bias,
        int K, int zInner, float alpha) {
    __shared__ float As[2][16 * PAD];
    __shared__ float Bs[2][16 * PAD];

    int z  = blockIdx.z;
    int zo = z / zInner, zi = z - zo * zInner;
    A += (size_t)zo * aOut + (size_t)zi * aIn;
    B += (size_t)zo * bOut + (size_t)zi * bIn;
    C += (size_t)zo * cOut + (size_t)zi * cIn;

    const int m0 = blockIdx.y * 128, n0 = blockIdx.x * 128;
    const int tid = threadIdx.x;
    const int tx4 = (tid & 15) << 2;          // col quad 0..60
    const int ty4 = (tid >> 4) << 2;          // row quad 0..60
    // A-side loader (also used for transposed B): 64 rows x 4 k-floats, x2 rows
    const int ar = tid >> 2;                  // 0..63
    const int ak = (tid & 3) << 2;            // 0,4,8,12
    // B-side loader (NN): 8 k-rows x 128 n, x2 rows
    const int bk = tid >> 5;                  // 0..7
    const int bn = (tid & 31) << 2;           // 0..124

    float acc[8][8] = {};
    float4 a0r, a1r, b0r, b1r;

    // ---- prologue: load k-tile 0 into regs, store to smem buf 0 ----
    {
        const float* Ap = A + (size_t)(m0 + ar) * lda + ak;
        a0r = *(const float4*)(Ap);
        a1r = *(const float4*)(Ap + (size_t)64 * lda);
        if (TRANSB) {
            const float* Bp = B + (size_t)(n0 + ar) * ldb + ak;
            b0r = *(const float4*)(Bp);
            b1r = *(const float4*)(Bp + (size_t)64 * ldb);
        } else {
            const float* Bp = B + (size_t)bk * ldb + n0 + bn;
            b0r = *(const float4*)(Bp);
            b1r = *(const float4*)(Bp + (size_t)8 * ldb);
        }
        float* as = As[0];
        as[(ak + 0) * PAD + ar] = a0r.x;
        as[(ak + 1) * PAD + ar] = a0r.y;
        as[(ak + 2) * PAD + ar] = a0r.z;
        as[(ak + 3) * PAD + ar] = a0r.w;
        as[(ak + 0) * PAD + ar + 64] = a1r.x;
        as[(ak + 1) * PAD + ar + 64] = a1r.y;
        as[(ak + 2) * PAD + ar + 64] = a1r.z;
        as[(ak + 3) * PAD + ar + 64] = a1r.w;
        float* bs = Bs[0];
        if (TRANSB) {
            bs[(ak + 0) * PAD + ar] = b0r.x;
            bs[(ak + 1) * PAD + ar] = b0r.y;
            bs[(ak + 2) * PAD + ar] = b0r.z;
            bs[(ak + 3) * PAD + ar] = b0r.w;
            bs[(ak + 0) * PAD + ar + 64] = b1r.x;
            bs[(ak + 1) * PAD + ar + 64] = b1r.y;
            bs[(ak + 2) * PAD + ar + 64] = b1r.z;
            bs[(ak + 3) * PAD + ar + 64] = b1r.w;
        } else {
            *(float4*)(bs + bk * PAD + bn)       = b0r;
            *(float4*)(bs + (bk + 8) * PAD + bn) = b1r;
        }
    }
    __syncthreads();

    const int nkt = K >> 4;
    for (int kt = 0; kt < nkt; kt++) {
        const int cur = kt & 1;
        if (kt + 1 < nkt) {
            const int k0 = (kt + 1) << 4;
            const float* Ap = A + (size_t)(m0 + ar) * lda + k0 + ak;
            a0r = *(const float4*)(Ap);
            a1r = *(const float4*)(Ap + (size_t)64 * lda);
            if (TRANSB) {
                const float* Bp = B + (size_t)(n0 + ar) * ldb + k0 + ak;
                b0r = *(const float4*)(Bp);
                b1r = *(const float4*)(Bp + (size_t)64 * ldb);
            } else {
                const float* Bp = B + (size_t)(k0 + bk) * ldb + n0 + bn;
                b0r = *(const float4*)(Bp);
                b1r = *(const float4*)(Bp + (size_t)8 * ldb);
            }
        }
        const float* as = As[cur];
        const float* bs = Bs[cur];
        #pragma unroll
        for (int k = 0; k < 16; k++) {
            float4 a0 = *(const float4*)(as + k * PAD + ty4);
            float4 a1 = *(const float4*)(as + k * PAD + ty4 + 64);
            float4 b0 = *(const float4*)(bs + k * PAD + tx4);
            float4 b1 = *(const float4*)(bs + k * PAD + tx4 + 64);
            float av[8] = {a0.x, a0.y, a0.z, a0.w, a1.x, a1.y, a1.z, a1.w};
            float bv[8] = {b0.x, b0.y, b0.z, b0.w, b1.x, b1.y, b1.z, b1.w};
            #pragma unroll
            for (int i = 0; i < 8; i++)
                #pragma unroll
                for (int j = 0; j < 8; j++)
                    acc[i][j] = fmaf(av[i], bv[j], acc[i][j]);
        }
        if (kt + 1 < nkt) {
            const int nxt = cur ^ 1;
            float* as2 = As[nxt];
            as2[(ak + 0) * PAD + ar] = a0r.x;
            as2[(ak + 1) * PAD + ar] = a0r.y;
            as2[(ak + 2) * PAD + ar] = a0r.z;
            as2[(ak + 3) * PAD + ar] = a0r.w;
            as2[(ak + 0) * PAD + ar + 64] = a1r.x;
            as2[(ak + 1) * PAD + ar + 64] = a1r.y;
            as2[(ak + 2) * PAD + ar + 64] = a1r.z;
            as2[(ak + 3) * PAD + ar + 64] = a1r.w;
            float* bs2 = Bs[nxt];
            if (TRANSB) {
                bs2[(ak + 0) * PAD + ar] = b0r.x;
                bs2[(ak + 1) * PAD + ar] = b0r.y;
                bs2[(ak + 2) * PAD + ar] = b0r.z;
                bs2[(ak + 3) * PAD + ar] = b0r.w;
                bs2[(ak + 0) * PAD + ar + 64] = b1r.x;
                bs2[(ak + 1) * PAD + ar + 64] = b1r.y;
                bs2[(ak + 2) * PAD + ar + 64] = b1r.z;
                bs2[(ak + 3) * PAD + ar + 64] = b1r.w;
            } else {
                *(float4*)(bs2 + bk * PAD + bn)       = b0r;
                *(float4*)(bs2 + (bk + 8) * PAD + bn) = b1r;
            }
            __syncthreads();
        }
    }

    // ---- epilogue ----
    float bvals[8];
    if (HASBIAS) {
        *(float4*)&bvals[0] = *(const float4*)(bias + n0 + tx4);
        *(float4*)&bvals[4] = *(const float4*)(bias + n0 + tx4 + 64);
    }
    #pragma unroll
    for (int i = 0; i < 8; i++) {
        int row = m0 + ((i < 4) ? (ty4 + i) : (64 + ty4 + i - 4));
        float4 o0, o1;
        float t0[4], t1[4];
        #pragma unroll
        for (int j = 0; j < 4; j++) {
            float v = acc[i][j] * alpha;
            if (HASBIAS) v += bvals[j];
            if (RELU)    v = fmaxf(v, 0.0f);
            t0[j] = v;
            float w = acc[i][j + 4] * alpha;
            if (HASBIAS) w += bvals[j + 4];
            if (RELU)    w = fmaxf(w, 0.0f);
            t1[j] = w;
        }
        o0 = make_float4(t0[0], t0[1], t0[2], t0[3]);
        o1 = make_float4(t1[0], t1[1], t1[2], t1[3]);
        *(float4*)(C + (size_t)row * ldc + n0 + tx4)      = o0;
        *(float4*)(C + (size_t)row * ldc + n0 + tx4 + 64) = o1;
    }
}

// ---------------------------------------------------------------------------
// Row softmax over 1024 columns; one block (256 threads) per row.
// ---------------------------------------------------------------------------
__global__ void k_softmax(float* __restrict__ S) {
    float* row = S + (size_t)blockIdx.x * 1024;
    int tid = threadIdx.x;
    float vals[4];
    float lmax = -INFINITY;
    #pragma unroll
    for (int i = 0; i < 4; i++) {
        vals[i] = row[tid + i * 256];
        lmax = fmaxf(lmax, vals[i]);
    }
    __shared__ float red[256];
    red[tid] = lmax;
    __syncthreads();
    for (int s = 128; s > 0; s >>= 1) {
        if (tid < s) red[tid] = fmaxf(red[tid], red[tid + s]);
        __syncthreads();
    }
    float m = red[0];
    __syncthreads();
    float lsum = 0.0f;
    #pragma unroll
    for (int i = 0; i < 4; i++) {
        vals[i] = __expf(vals[i] - m);
        lsum += vals[i];
    }
    red[tid] = lsum;
    __syncthreads();
    for (int s = 128; s > 0; s >>= 1) {
        if (tid < s) red[tid] += red[tid + s];
        __syncthreads();
    }
    float inv = 1.0f / red[0];
    #pragma unroll
    for (int i = 0; i < 4; i++) row[tid + i * 256] = vals[i] * inv;
}

// ---------------------------------------------------------------------------
// Row normalize: (x - mean) / (std_ddof1 + 1e-8). One block (128 thr) per row.
// ---------------------------------------------------------------------------
__global__ void k_rownorm(const float* __restrict__ feat,
                          float*       __restrict__ out) {
    int tid = threadIdx.x;
    size_t base = (size_t)blockIdx.x * DD_;
    float x = feat[base + tid];
    __shared__ float red[4];
    float s = x;
    #pragma unroll
    for (int o = 16; o > 0; o >>= 1) s += __shfl_xor_sync(0xffffffffu, s, o);
    if ((tid & 31) == 0) red[tid >> 5] = s;
    __syncthreads();
    float mu = (red[0] + red[1] + red[2] + red[3]) * (1.0f / 128.0f);
    float d = x - mu;
    float ss = d * d;
    #pragma unroll
    for (int o = 16; o > 0; o >>= 1) ss += __shfl_xor_sync(0xffffffffu, ss, o);
    __syncthreads();
    if ((tid & 31) == 0) red[tid >> 5] = ss;
    __syncthreads();
    float var = (red[0] + red[1] + red[2] + red[3]) * (1.0f / 127.0f);
    float inv = 1.0f / (sqrtf(var) + 1e-8f);
    out[base + tid] = d * inv;
}

// ---------------------------------------------------------------------------
extern "C" void kernel_launch(void* const* d_in, const int* in_sizes, int n_in,
                              void* d_out, int out_size) {
    const float* A_t = (const float*)d_in[0];
    const float* F_c = (const float*)d_in[1];
    const int*   t   = (const int*)  d_in[2];
    const float* Wq  = (const float*)d_in[3];
    const float* bq  = (const float*)d_in[4];
    const float* Wk  = (const float*)d_in[5];
    const float* bk  = (const float*)d_in[6];
    const float* Wv  = (const float*)d_in[7];
    const float* bv  = (const float*)d_in[8];
    const float* Wo  = (const float*)d_in[9];
    const float* bo  = (const float*)d_in[10];
    const float* Wg  = (const float*)d_in[11];
    float* out = (float*)d_out;

    float *c, *q, *k, *v, *s, *ctx, *h, *hw, *feat, *nrm;
    cudaGetSymbolAddress((void**)&c,    g_c);
    cudaGetSymbolAddress((void**)&q,    g_q);
    cudaGetSymbolAddress((void**)&k,    g_k);
    cudaGetSymbolAddress((void**)&v,    g_v);
    cudaGetSymbolAddress((void**)&s,    g_s);
    cudaGetSymbolAddress((void**)&ctx,  g_ctx);
    cudaGetSymbolAddress((void**)&h,    g_h);
    cudaGetSymbolAddress((void**)&hw,   g_hw);
    cudaGetSymbolAddress((void**)&feat, g_feat);
    cudaGetSymbolAddress((void**)&nrm,  g_norm);

    const size_t sBN  = (size_t)NN_ * HH_ * DD_;    // 1M  (q/k/v/ctx per batch)
    const size_t sBD  = (size_t)NN_ * DD_;          // 128K
    const size_t sNN  = (size_t)NN_ * NN_;          // 1M  (per-head scores / per-batch out)
    const float  scl  = 0.08838834764831845f;       // 1/sqrt(128)

    // 1) c = F_c + t_emb
    k_embed_add<<<BSZ * NN_, DD_>>>(F_c, t, c);

    // 2) QKV projections: [1024,128]@[128,1024]+bias, batched over 16
    {
        dim3 g(8, 8, BSZ);
        gemm128<false, true, false><<<g, 256>>>(c, DD_, sBD, 0,
                                                Wq, HH_ * DD_, 0, 0,
                                                q, HH_ * DD_, sBN, 0,
                                                bq, DD_, 1, 1.0f);
        gemm128<false, true, false><<<g, 256>>>(c, DD_, sBD, 0,
                                                Wk, HH_ * DD_, 0, 0,
                                                k, HH_ * DD_, sBN, 0,
                                                bk, DD_, 1, 1.0f);
        gemm128<false, true, false><<<g, 256>>>(c, DD_, sBD, 0,
                                                Wv, HH_ * DD_, 0, 0,
                                                v, HH_ * DD_, sBN, 0,
                                                bv, DD_, 1, 1.0f);
    }

    // 3a) scores[b,h] = scl * Q_bh @ K_bh^T   (batched over 128 b*h)
    {
        dim3 g(8, 8, BSZ * HH_);
        gemm128<false, false, true><<<g, 256>>>(q, HH_ * DD_, sBN, DD_,
                                                k, HH_ * DD_, sBN, DD_,
                                                s, NN_, (size_t)HH_ * sNN, sNN,
                                                nullptr, DD_, HH_, scl);
    }
    // 3b) softmax over all rows
    k_softmax<<<BSZ * HH_ * NN_, 256>>>(s);

    // 3c) ctx[b,h] = P_bh @ V_bh  (store [b, n, h*128+d])
    {
        dim3 g(1, 8, BSZ * HH_);
        gemm128<false, false, false><<<g, 256>>>(s, NN_, (size_t)HH_ * sNN, sNN,
                                                 v, HH_ * DD_, sBN, DD_,
                                                 ctx, HH_ * DD_, sBN, DD_,
                                                 nullptr, NN_, HH_, 1.0f);
    }

    // 4) h = ctx @ Wo + bo
    {
        dim3 g(1, 8, BSZ);
        gemm128<false, true, false><<<g, 256>>>(ctx, HH_ * DD_, sBN, 0,
                                                Wo, DD_, 0, 0,
                                                h, DD_, sBD, 0,
                                                bo, HH_ * DD_, 1, 1.0f);
    }
    // 5) hw = h @ Wg
    {
        dim3 g(1, 8, BSZ);
        gemm128<false, false, false><<<g, 256>>>(h, DD_, sBD, 0,
                                                 Wg, DD_, 0, 0,
                                                 hw, DD_, sBD, 0,
                                                 nullptr, DD_, 1, 1.0f);
    }
    // 6) feat = relu(A_t @ hw)
    {
        dim3 g(1, 8, BSZ);
        gemm128<true, false, false><<<g, 256>>>(A_t, NN_, sNN, 0,
                                                hw, DD_, sBD, 0,
                                                feat, DD_, sBD, 0,
                                                nullptr, NN_, 1, 1.0f);
    }
    // 7) row normalize
    k_rownorm<<<BSZ * NN_, DD_>>>(feat, nrm);

    // 8) out = (norm @ norm^T) / 128
    {
        dim3 g(8, 8, BSZ);
        gemm128<false, false, true><<<g, 256>>>(nrm, DD_, sBD, 0,
                                                nrm, DD_, sBD, 0,
                                                out, NN_, sNN, 0,
                                                nullptr, DD_, 1, 1.0f / 128.0f);
    }
}

// round 4
// speedup vs baseline: 1.7141x; 1.0095x over previous
#include <cuda_runtime.h>
#include <math.h>
#include <stdint.h>

#define BSZ 16
#define NN_ 1024
#define DD_ 128
#define HH_ 8

// ---------------------------------------------------------------------------
// Static scratch
// ---------------------------------------------------------------------------
__device__ float g_c   [BSZ * NN_ * DD_];
__device__ float g_q   [BSZ * NN_ * HH_ * DD_];
__device__ float g_k   [BSZ * NN_ * HH_ * DD_];
__device__ float g_v   [BSZ * NN_ * HH_ * DD_];
__device__ float g_s   [134217728];                 // 512 MB [b, h, n, m]
__device__ float g_ctx [BSZ * NN_ * HH_ * DD_];
__device__ float g_h   [BSZ * NN_ * DD_];
__device__ float g_hw  [BSZ * NN_ * DD_];
__device__ float g_feat[BSZ * NN_ * DD_];
__device__ float g_norm[BSZ * NN_ * DD_];

// ---------------------------------------------------------------------------
__device__ __forceinline__ uint32_t tf32r(float x) {   // round-to-nearest tf32
    uint32_t u;
    asm("cvt.rna.tf32.f32 %0, %1;" : "=r"(u) : "f"(x));
    return u;
}
__device__ __forceinline__ void mma_tf32(float* d, const uint32_t* a, const uint32_t* b) {
    asm volatile(
        "mma.sync.aligned.m16n8k8.row.col.f32.tf32.tf32.f32 "
        "{%0,%1,%2,%3}, {%4,%5,%6,%7}, {%8,%9}, {%0,%1,%2,%3};"
        : "+f"(d[0]), "+f"(d[1]), "+f"(d[2]), "+f"(d[3])
        : "r"(a[0]), "r"(a[1]), "r"(a[2]), "r"(a[3]), "r"(b[0]), "r"(b[1]));
}

// ---------------------------------------------------------------------------
// tf32 tensor-core GEMM via mma.sync m16n8k8.
// C = alpha * A @ B(^T) (+bias) (+relu)
// A [M,K] row-major lda. B: TRANSB ? [N,K] : [K,N] row-major ldb. C [M,N] ldc.
// Tile 128x128x16, 256 threads = 8 warps (4 along M x 2 along N).
// Warp tile 32(m) x 64(n): 2 m16-tiles x 8 n8-tiles. Double buffered.
// SMEM holds operands pre-permuted into mma fragment order:
//   A frag addr = (((warp_m*2+kk)*2+mt)*32 + lane)*4 + reg   (reg = rk*2+rm)
//   B frag addr = (((warp_n*2+kk)*8+nt)*32 + lane)*2 + reg   (reg = rk)
// where lane = g*4+tig, g = row-in-tile&7 (A) / col&7 (B), tig = k&3,
//       rm = (row-in-tile)>>3, rk = (k>>2)&1, kk = k>>3.
// Requires M,N multiples of 128; K multiple of 16.
// z = blockIdx.z -> zo = z/zInner, zi = z%zInner; ptr += zo*Out + zi*In.
// ---------------------------------------------------------------------------
template<bool RELU, bool HASBIAS, bool TRANSB>
__global__ void __launch_bounds__(256)
gemm_mma(const float* __restrict__ A, int lda, size_t aOut, size_t aIn,
         const float* __restrict__ B, int ldb, size_t bOut, size_t bIn,
         float*       __restrict__ C, int ldc, size_t cOut, size_t cIn,
         const float* __restrict__ bias,
         int K, int zInner, float alpha) {
    __shared__ uint32_t sAf[2][2048];   // 8 KB per buffer
    __shared__ uint32_t sBf[2][2048];

    const int tid  = threadIdx.x;
    const int wid  = tid >> 5;
    const int lane = tid & 31;
    const int warp_m = wid & 3;
    const int warp_n = wid >> 2;
    const int g   = lane >> 2;
    const int tig = lane & 3;

    int z  = blockIdx.z;
    int zo = z / zInner, zi = z - zo * zInner;
    A += (size_t)zo * aOut + (size_t)zi * aIn;
    B += (size_t)zo * bOut + (size_t)zi * bIn;
    C += (size_t)zo * cOut + (size_t)zi * cIn;

    const int m0 = blockIdx.y * 128, n0 = blockIdx.x * 128;

    // staging decomposition (constant per thread)
    const int uA0 = tid, uA1 = tid + 256;        // A/B-transb units: m|n = u>>2, qk = u&3
    // A unit geometry
    const int amA0 = uA0 >> 2, aqk0 = uA0 & 3;
    const int amA1 = uA1 >> 2, aqk1 = uA1 & 3;

    float acc[2][8][4];
    #pragma unroll
    for (int mt = 0; mt < 2; mt++)
        #pragma unroll
        for (int nt = 0; nt < 8; nt++)
            #pragma unroll
            for (int r = 0; r < 4; r++) acc[mt][nt][r] = 0.0f;

    float4 pa[2], pb[2];

    // scatter-store helpers --------------------------------------------------
    // A-pattern scatter (also used for TRANSB B with the B frag layout)
    auto scatA = [&](uint32_t* dst, int m, int qk, float4 v) {
        int wm = m >> 5, mt = (m >> 4) & 1, rowin = m & 15;
        int gg = rowin & 7, rm = rowin >> 3;
        int kk = qk >> 1, rk = qk & 1;
        int reg = rk * 2 + rm;
        uint32_t base = (uint32_t)((((wm * 2 + kk) * 2 + mt) * 32 + gg * 4) * 4 + reg);
        dst[base + 0]  = tf32r(v.x);
        dst[base + 4]  = tf32r(v.y);
        dst[base + 8]  = tf32r(v.z);
        dst[base + 12] = tf32r(v.w);
    };
    auto scatBt = [&](uint32_t* dst, int n, int qk, float4 v) {
        int wn = n >> 6, nt = (n >> 3) & 7, gg = n & 7;
        int kk = qk >> 1, rk = qk & 1;
        uint32_t base = (uint32_t)((((wn * 2 + kk) * 8 + nt) * 32 + gg * 4) * 2 + rk);
        dst[base + 0] = tf32r(v.x);
        dst[base + 2] = tf32r(v.y);
        dst[base + 4] = tf32r(v.z);
        dst[base + 6] = tf32r(v.w);
    };
    auto scatBn = [&](uint32_t* dst, int k, int qn, float4 v) {
        int kk = k >> 3, rk = (k >> 2) & 1, tg = k & 3;
        int wn = qn >> 4, nt = (qn >> 1) & 7;
        int g0 = (qn & 1) * 4;
        uint32_t base = (uint32_t)((((wn * 2 + kk) * 8 + nt) * 32 + g0 * 4 + tg) * 2 + rk);
        dst[base + 0]  = tf32r(v.x);
        dst[base + 8]  = tf32r(v.y);
        dst[base + 16] = tf32r(v.z);
        dst[base + 24] = tf32r(v.w);
    };
    auto loadTile = [&](int k0) {
        pa[0] = *(const float4*)(A + (size_t)(m0 + amA0) * lda + k0 + aqk0 * 4);
        pa[1] = *(const float4*)(A + (size_t)(m0 + amA1) * lda + k0 + aqk1 * 4);
        if (TRANSB) {
            pb[0] = *(const float4*)(B + (size_t)(n0 + amA0) * ldb + k0 + aqk0 * 4);
            pb[1] = *(const float4*)(B + (size_t)(n0 + amA1) * ldb + k0 + aqk1 * 4);
        } else {
            int k_0 = uA0 >> 5, qn0 = uA0 & 31;
            int k_1 = uA1 >> 5, qn1 = uA1 & 31;
            pb[0] = *(const float4*)(B + (size_t)(k0 + k_0) * ldb + n0 + qn0 * 4);
            pb[1] = *(const float4*)(B + (size_t)(k0 + k_1) * ldb + n0 + qn1 * 4);
        }
    };
    auto storeTile = [&](int buf) {
        scatA(sAf[buf], amA0, aqk0, pa[0]);
        scatA(sAf[buf], amA1, aqk1, pa[1]);
        if (TRANSB) {
            scatBt(sBf[buf], amA0, aqk0, pb[0]);
            scatBt(sBf[buf], amA1, aqk1, pb[1]);
        } else {
            scatBn(sBf[buf], uA0 >> 5, uA0 & 31, pb[0]);
            scatBn(sBf[buf], uA1 >> 5, uA1 & 31, pb[1]);
        }
    };

    // prologue
    loadTile(0);
    storeTile(0);
    __syncthreads();

    const int nkt = K >> 4;
    for (int kt = 0; kt < nkt; kt++) {
        const int cur = kt & 1;
        if (kt + 1 < nkt) loadTile((kt + 1) << 4);

        const uint32_t* aB = sAf[cur];
        const uint32_t* bB = sBf[cur];
        #pragma unroll
        for (int kk = 0; kk < 2; kk++) {
            uint32_t afr[2][4];
            #pragma unroll
            for (int mt = 0; mt < 2; mt++) {
                const uint4 u = *(const uint4*)(aB + (((warp_m * 2 + kk) * 2 + mt) * 32 + lane) * 4);
                afr[mt][0] = u.x; afr[mt][1] = u.y; afr[mt][2] = u.z; afr[mt][3] = u.w;
            }
            uint32_t bfr[8][2];
            #pragma unroll
            for (int nt = 0; nt < 8; nt++) {
                const uint2 u = *(const uint2*)(bB + (((warp_n * 2 + kk) * 8 + nt) * 32 + lane) * 2);
                bfr[nt][0] = u.x; bfr[nt][1] = u.y;
            }
            #pragma unroll
            for (int mt = 0; mt < 2; mt++)
                #pragma unroll
                for (int nt = 0; nt < 8; nt++)
                    mma_tf32(acc[mt][nt], afr[mt], bfr[nt]);
        }
        if (kt + 1 < nkt) {
            __syncthreads();
            storeTile(cur ^ 1);
            __syncthreads();
        }
    }

    // epilogue: c0,c1 -> (row, col..col+1); c2,c3 -> (row+8, ...)
    #pragma unroll
    for (int mt = 0; mt < 2; mt++) {
        const int row = m0 + warp_m * 32 + mt * 16 + g;
        #pragma unroll
        for (int nt = 0; nt < 8; nt++) {
            const int col = n0 + warp_n * 64 + nt * 8 + tig * 2;
            float v0 = acc[mt][nt][0] * alpha;
            float v1 = acc[mt][nt][1] * alpha;
            float v2 = acc[mt][nt][2] * alpha;
            float v3 = acc[mt][nt][3] * alpha;
            if (HASBIAS) {
                float b0 = bias[col], b1 = bias[col + 1];
                v0 += b0; v1 += b1; v2 += b0; v3 += b1;
            }
            if (RELU) {
                v0 = fmaxf(v0, 0.0f); v1 = fmaxf(v1, 0.0f);
                v2 = fmaxf(v2, 0.0f); v3 = fmaxf(v3, 0.0f);
            }
            *(float2*)(C + (size_t)row * ldc + col)       = make_float2(v0, v1);
            *(float2*)(C + (size_t)(row + 8) * ldc + col) = make_float2(v2, v3);
        }
    }
}

// ---------------------------------------------------------------------------
// c = F_c + timestep_emb(t)[:, :, None]
// ---------------------------------------------------------------------------
__global__ void k_embed_add(const float* __restrict__ F_c,
                            const int*   __restrict__ t,
                            float*       __restrict__ c) {
    int bn = blockIdx.x;
    int b  = bn >> 10;
    int n  = bn & 1023;
    float tv = (float)t[b];
    const float kC = logf(1000.0f) / 511.0f;
    int   i = (n < 512) ? n : (n - 512);
    float f = __expf(-(float)i * kC);
    float e = tv * f;
    float emb = (n < 512) ? sinf(e) : cosf(e);
    size_t base = (size_t)bn * DD_;
    int d = threadIdx.x;
    c[base + d] = F_c[base + d] + emb;
}

// ---------------------------------------------------------------------------
// Row softmax over 1024 columns; one block (256 threads) per row.
// ---------------------------------------------------------------------------
__global__ void k_softmax(float* __restrict__ S) {
    float* row = S + (size_t)blockIdx.x * 1024;
    int tid = threadIdx.x;
    float vals[4];
    float lmax = -INFINITY;
    #pragma unroll
    for (int i = 0; i < 4; i++) {
        vals[i] = row[tid + i * 256];
        lmax = fmaxf(lmax, vals[i]);
    }
    __shared__ float red[256];
    red[tid] = lmax;
    __syncthreads();
    for (int s = 128; s > 0; s >>= 1) {
        if (tid < s) red[tid] = fmaxf(red[tid], red[tid + s]);
        __syncthreads();
    }
    float m = red[0];
    __syncthreads();
    float lsum = 0.0f;
    #pragma unroll
    for (int i = 0; i < 4; i++) {
        vals[i] = __expf(vals[i] - m);
        lsum += vals[i];
    }
    red[tid] = lsum;
    __syncthreads();
    for (int s = 128; s > 0; s >>= 1) {
        if (tid < s) red[tid] += red[tid + s];
        __syncthreads();
    }
    float inv = 1.0f / red[0];
    #pragma unroll
    for (int i = 0; i < 4; i++) row[tid + i * 256] = vals[i] * inv;
}

// ---------------------------------------------------------------------------
// Row normalize: (x - mean) / (std_ddof1 + 1e-8). One block (128 thr) per row.
// ---------------------------------------------------------------------------
__global__ void k_rownorm(const float* __restrict__ feat,
                          float*       __restrict__ out) {
    int tid = threadIdx.x;
    size_t base = (size_t)blockIdx.x * DD_;
    float x = feat[base + tid];
    __shared__ float red[4];
    float s = x;
    #pragma unroll
    for (int o = 16; o > 0; o >>= 1) s += __shfl_xor_sync(0xffffffffu, s, o);
    if ((tid & 31) == 0) red[tid >> 5] = s;
    __syncthreads();
    float mu = (red[0] + red[1] + red[2] + red[3]) * (1.0f / 128.0f);
    float d = x - mu;
    float ss = d * d;
    #pragma unroll
    for (int o = 16; o > 0; o >>= 1) ss += __shfl_xor_sync(0xffffffffu, ss, o);
    __syncthreads();
    if ((tid & 31) == 0) red[tid >> 5] = ss;
    __syncthreads();
    float var = (red[0] + red[1] + red[2] + red[3]) * (1.0f / 127.0f);
    float inv = 1.0f / (sqrtf(var) + 1e-8f);
    out[base + tid] = d * inv;
}

// ---------------------------------------------------------------------------
extern "C" void kernel_launch(void* const* d_in, const int* in_sizes, int n_in,
                              void* d_out, int out_size) {
    const float* A_t = (const float*)d_in[0];
    const float* F_c = (const float*)d_in[1];
    const int*   t   = (const int*)  d_in[2];
    const float* Wq  = (const float*)d_in[3];
    const float* bq  = (const float*)d_in[4];
    const float* Wk  = (const float*)d_in[5];
    const float* bk  = (const float*)d_in[6];
    const float* Wv  = (const float*)d_in[7];
    const float* bv  = (const float*)d_in[8];
    const float* Wo  = (const float*)d_in[9];
    const float* bo  = (const float*)d_in[10];
    const float* Wg  = (const float*)d_in[11];
    float* out = (float*)d_out;

    float *c, *q, *k, *v, *s, *ctx, *h, *hw, *feat, *nrm;
    cudaGetSymbolAddress((void**)&c,    g_c);
    cudaGetSymbolAddress((void**)&q,    g_q);
    cudaGetSymbolAddress((void**)&k,    g_k);
    cudaGetSymbolAddress((void**)&v,    g_v);
    cudaGetSymbolAddress((void**)&s,    g_s);
    cudaGetSymbolAddress((void**)&ctx,  g_ctx);
    cudaGetSymbolAddress((void**)&h,    g_h);
    cudaGetSymbolAddress((void**)&hw,   g_hw);
    cudaGetSymbolAddress((void**)&feat, g_feat);
    cudaGetSymbolAddress((void**)&nrm,  g_norm);

    const size_t sBN = (size_t)NN_ * HH_ * DD_;   // 1M
    const size_t sBD = (size_t)NN_ * DD_;         // 128K
    const size_t sNN = (size_t)NN_ * NN_;         // 1M
    const float  scl = 0.08838834764831845f;      // 1/sqrt(128)

    k_embed_add<<<BSZ * NN_, DD_>>>(F_c, t, c);

    // QKV: [1024,128]@[128,1024]+bias, 16 batches
    {
        dim3 g(8, 8, BSZ);
        gemm_mma<false, true, false><<<g, 256>>>(c, DD_, sBD, 0,
                                                 Wq, HH_ * DD_, 0, 0,
                                                 q, HH_ * DD_, sBN, 0,
                                                 bq, DD_, 1, 1.0f);
        gemm_mma<false, true, false><<<g, 256>>>(c, DD_, sBD, 0,
                                                 Wk, HH_ * DD_, 0, 0,
                                                 k, HH_ * DD_, sBN, 0,
                                                 bk, DD_, 1, 1.0f);
        gemm_mma<false, true, false><<<g, 256>>>(c, DD_, sBD, 0,
                                                 Wv, HH_ * DD_, 0, 0,
                                                 v, HH_ * DD_, sBN, 0,
                                                 bv, DD_, 1, 1.0f);
    }

    // scores[b,h] = scl * Q @ K^T    (128 batch-heads)
    {
        dim3 g(8, 8, BSZ * HH_);
        gemm_mma<false, false, true><<<g, 256>>>(q, HH_ * DD_, sBN, DD_,
                                                 k, HH_ * DD_, sBN, DD_,
                                                 s, NN_, (size_t)HH_ * sNN, sNN,
                                                 nullptr, DD_, HH_, scl);
    }
    k_softmax<<<BSZ * HH_ * NN_, 256>>>(s);

    // ctx[b,h] = P @ V
    {
        dim3 g(1, 8, BSZ * HH_);
        gemm_mma<false, false, false><<<g, 256>>>(s, NN_, (size_t)HH_ * sNN, sNN,
                                                  v, HH_ * DD_, sBN, DD_,
                                                  ctx, HH_ * DD_, sBN, DD_,
                                                  nullptr, NN_, HH_, 1.0f);
    }

    // h = ctx @ Wo + bo
    {
        dim3 g(1, 8, BSZ);
        gemm_mma<false, true, false><<<g, 256>>>(ctx, HH_ * DD_, sBN, 0,
                                                 Wo, DD_, 0, 0,
                                                 h, DD_, sBD, 0,
                                                 bo, HH_ * DD_, 1, 1.0f);
    }
    // hw = h @ Wg
    {
        dim3 g(1, 8, BSZ);
        gemm_mma<false, false, false><<<g, 256>>>(h, DD_, sBD, 0,
                                                  Wg, DD_, 0, 0,
                                                  hw, DD_, sBD, 0,
                                                  nullptr, DD_, 1, 1.0f);
    }
    // feat = relu(A_t @ hw)
    {
        dim3 g(1, 8, BSZ);
        gemm_mma<true, false, false><<<g, 256>>>(A_t, NN_, sNN, 0,
                                                 hw, DD_, sBD, 0,
                                                 feat, DD_, sBD, 0,
                                                 nullptr, NN_, 1, 1.0f);
    }
    k_rownorm<<<BSZ * NN_, DD_>>>(feat, nrm);

    // out = (norm @ norm^T) / 128
    {
        dim3 g(8, 8, BSZ);
        gemm_mma<false, false, true><<<g, 256>>>(nrm, DD_, sBD, 0,
                                                 nrm, DD_, sBD, 0,
                                                 out, NN_, sNN, 0,
                                                 nullptr, DD_, 1, 1.0f / 128.0f);
    }
}

// round 5
// speedup vs baseline: 2.4370x; 1.4218x over previous
#include <cuda_runtime.h>
#include <math.h>
#include <stdint.h>

#define BSZ 16
#define NN_ 1024
#define DD_ 128
#define HH_ 8

// ---------------------------------------------------------------------------
// Static scratch
// ---------------------------------------------------------------------------
__device__ float g_c   [BSZ * NN_ * DD_];
__device__ float g_q   [BSZ * NN_ * HH_ * DD_];      // [b, n, hd]
__device__ float g_k   [BSZ * NN_ * HH_ * DD_];      // [b, n, hd]
__device__ float g_vt  [BSZ * NN_ * HH_ * DD_];      // [b, hd, n]  (V^T)
__device__ float g_s   [134217728];                  // 512 MB [b, h, n, m]
__device__ float g_ctx [BSZ * NN_ * HH_ * DD_];      // [b, n, hd]
__device__ float g_h   [BSZ * NN_ * DD_];
__device__ float g_hwt [BSZ * NN_ * DD_];            // [b, d, n]  (hw^T)
__device__ float g_feat[BSZ * NN_ * DD_];
__device__ float g_norm[BSZ * NN_ * DD_];
__device__ float g_wqT [NN_ * DD_];                  // [1024,128]
__device__ float g_wkT [NN_ * DD_];
__device__ float g_wvT [NN_ * DD_];
__device__ float g_woT [NN_ * DD_];                  // [128,1024]
__device__ float g_wgT [DD_ * DD_];

// ---------------------------------------------------------------------------
__device__ __forceinline__ uint32_t tf32r(float x) {   // round-to-nearest tf32
    uint32_t u;
    asm("cvt.rna.tf32.f32 %0, %1;" : "=r"(u) : "f"(x));
    return u;
}
__device__ __forceinline__ void mma_tf32(float* d, const uint32_t* a, const uint32_t* b) {
    asm volatile(
        "mma.sync.aligned.m16n8k8.row.col.f32.tf32.tf32.f32 "
        "{%0,%1,%2,%3}, {%4,%5,%6,%7}, {%8,%9}, {%0,%1,%2,%3};"
        : "+f"(d[0]), "+f"(d[1]), "+f"(d[2]), "+f"(d[3])
        : "r"(a[0]), "r"(a[1]), "r"(a[2]), "r"(a[3]), "r"(b[0]), "r"(b[1]));
}
__device__ __forceinline__ uint4 cvt4(float4 v) {
    uint4 u;
    u.x = tf32r(v.x); u.y = tf32r(v.y); u.z = tf32r(v.z); u.w = tf32r(v.w);
    return u;
}

// ---------------------------------------------------------------------------
// tf32 tensor-core GEMM: C = alpha * A @ B^T (+bias) (+relu), optional C^T out.
// A [M,K] row-major lda. B [N,K] row-major ldb (K-major, "TRANSB" form only).
// C: CT ? [N,M] (addr col*ldc+row) : [M,N] (addr row*ldc+col).
// Tile 128x128x16, 256 threads = 8 warps (warp_m = wid&3, warp_n = wid>>2),
// warp tile 32(m) x 64(n). Double-buffered SMEM in "reg-outer" frag layout:
//   A word = (((wm*2+kk)*2+mt)*4 + reg)*32 + lane      reg = rk*2+rm
//   B word = ((((wn*2+kk)*8+nt)*2 + rk)*32 + lane
// Staging: thread (w=wid, qk=lane>>3, gg=lane&7) loads rows (w*16+gg, +8),
// k-quad qk -> conflict-free STS.128; frag loads are stride-1 LDS.32.
// Requires M,N multiples of 128; K multiple of 16.
// z = blockIdx.z -> zo = z/zInner, zi = z%zInner; ptr += zo*Out + zi*In.
// ---------------------------------------------------------------------------
template<bool RELU, bool HASBIAS, bool CT>
__global__ void __launch_bounds__(256)
gemm_tb(const float* __restrict__ A, int lda, size_t aOut, size_t aIn,
        const float* __restrict__ B, int ldb, size_t bOut, size_t bIn,
        float*       __restrict__ C, int ldc, size_t cOut, size_t cIn,
        const float* __restrict__ bias,
        int K, int zInner, float alpha) {
    __shared__ uint32_t sA[2][2048];   // 8 KB each
    __shared__ uint32_t sB[2][2048];

    const int tid  = threadIdx.x;
    const int wid  = tid >> 5;
    const int lane = tid & 31;
    const int warp_m = wid & 3;
    const int warp_n = wid >> 2;
    const int g   = lane >> 2;          // mma row/col group
    const int tig = lane & 3;

    int z  = blockIdx.z;
    int zo = z / zInner, zi = z - zo * zInner;
    A += (size_t)zo * aOut + (size_t)zi * aIn;
    B += (size_t)zo * bOut + (size_t)zi * bIn;
    C += (size_t)zo * cOut + (size_t)zi * cIn;

    const int m0 = blockIdx.y * 128, n0 = blockIdx.x * 128;

    // ---- staging coordinates ----
    const int sw = wid;                 // 16-row block index 0..7
    const int qk = lane >> 3;           // k-quad 0..3
    const int gg = lane & 7;            // row-in-8
    const int rk = qk & 1, kk0 = qk >> 1;

    // store word bases (16B-aligned: multiples of 4 words)
    const uint32_t aSt0 = ((((((sw >> 1) * 2 + kk0) * 2) + (sw & 1)) * 4 + rk * 2) * 32) + gg * 4;
    const uint32_t aSt1 = aSt0 + 32;                                   // rm=1
    const uint32_t bSt0 = (((((sw >> 2) * 2 + kk0) * 8 + ((sw * 2) & 7)) * 2 + rk) * 32) + gg * 4;
    const uint32_t bSt1 = bSt0 + 64;                                   // nt+1

    const float* Ap = A + (size_t)(m0 + sw * 16 + gg) * lda + qk * 4;
    const float* Bp = B + (size_t)(n0 + sw * 16 + gg) * ldb + qk * 4;
    const size_t a8 = (size_t)8 * lda, b8 = (size_t)8 * ldb;

    float acc[2][8][4];
    #pragma unroll
    for (int mt = 0; mt < 2; mt++)
        #pragma unroll
        for (int nt = 0; nt < 8; nt++)
            #pragma unroll
            for (int r = 0; r < 4; r++) acc[mt][nt][r] = 0.0f;

    float4 ra0, ra1, rb0, rb1;

    // prologue
    ra0 = *(const float4*)(Ap);
    ra1 = *(const float4*)(Ap + a8);
    rb0 = *(const float4*)(Bp);
    rb1 = *(const float4*)(Bp + b8);
    *(uint4*)&sA[0][aSt0] = cvt4(ra0);
    *(uint4*)&sA[0][aSt1] = cvt4(ra1);
    *(uint4*)&sB[0][bSt0] = cvt4(rb0);
    *(uint4*)&sB[0][bSt1] = cvt4(rb1);
    __syncthreads();

    const int nkt = K >> 4;
    for (int kt = 0; kt < nkt; kt++) {
        const int cur = kt & 1;
        if (kt + 1 < nkt) {
            const int k0 = (kt + 1) << 4;
            ra0 = *(const float4*)(Ap + k0);
            ra1 = *(const float4*)(Ap + k0 + a8);
            rb0 = *(const float4*)(Bp + k0);
            rb1 = *(const float4*)(Bp + k0 + b8);
        }
        const uint32_t* aB = sA[cur];
        const uint32_t* bB = sB[cur];
        #pragma unroll
        for (int kk = 0; kk < 2; kk++) {
            uint32_t af[2][4];
            #pragma unroll
            for (int mt = 0; mt < 2; mt++) {
                const uint32_t base = (((warp_m * 2 + kk) * 2 + mt) * 4) * 32 + lane;
                af[mt][0] = aB[base];
                af[mt][1] = aB[base + 32];
                af[mt][2] = aB[base + 64];
                af[mt][3] = aB[base + 96];
            }
            uint32_t bf[8][2];
            #pragma unroll
            for (int nt = 0; nt < 8; nt++) {
                const uint32_t base = ((((warp_n * 2 + kk) * 8 + nt) * 2) * 32) + lane;
                bf[nt][0] = bB[base];
                bf[nt][1] = bB[base + 32];
            }
            #pragma unroll
            for (int mt = 0; mt < 2; mt++)
                #pragma unroll
                for (int nt = 0; nt < 8; nt++)
                    mma_tf32(acc[mt][nt], af[mt], bf[nt]);
        }
        if (kt + 1 < nkt) {
            const int nxt = cur ^ 1;
            __syncthreads();
            *(uint4*)&sA[nxt][aSt0] = cvt4(ra0);
            *(uint4*)&sA[nxt][aSt1] = cvt4(ra1);
            *(uint4*)&sB[nxt][bSt0] = cvt4(rb0);
            *(uint4*)&sB[nxt][bSt1] = cvt4(rb1);
            __syncthreads();
        }
    }

    // ---- epilogue ----
    #pragma unroll
    for (int mt = 0; mt < 2; mt++) {
        const int row = m0 + warp_m * 32 + mt * 16 + g;
        #pragma unroll
        for (int nt = 0; nt < 8; nt++) {
            const int col = n0 + warp_n * 64 + nt * 8 + tig * 2;
            float v0 = acc[mt][nt][0] * alpha;
            float v1 = acc[mt][nt][1] * alpha;
            float v2 = acc[mt][nt][2] * alpha;
            float v3 = acc[mt][nt][3] * alpha;
            if (HASBIAS) {
                float b0 = bias[col], b1 = bias[col + 1];
                v0 += b0; v1 += b1; v2 += b0; v3 += b1;
            }
            if (RELU) {
                v0 = fmaxf(v0, 0.0f); v1 = fmaxf(v1, 0.0f);
                v2 = fmaxf(v2, 0.0f); v3 = fmaxf(v3, 0.0f);
            }
            if (CT) {
                C[(size_t)col * ldc + row]           = v0;
                C[(size_t)(col + 1) * ldc + row]     = v1;
                C[(size_t)col * ldc + row + 8]       = v2;
                C[(size_t)(col + 1) * ldc + row + 8] = v3;
            } else {
                *(float2*)(C + (size_t)row * ldc + col)       = make_float2(v0, v1);
                *(float2*)(C + (size_t)(row + 8) * ldc + col) = make_float2(v2, v3);
            }
        }
    }
}

// ---------------------------------------------------------------------------
// 32x32 tiled transpose: out[C,R] = in[R,C]^T
// ---------------------------------------------------------------------------
__global__ void k_transpose(const float* __restrict__ in, float* __restrict__ out,
                            int R, int C) {
    __shared__ float t[32][33];
    int bx = blockIdx.x * 32, by = blockIdx.y * 32;
    #pragma unroll
    for (int i = 0; i < 32; i += 8)
        t[threadIdx.y + i][threadIdx.x] = in[(size_t)(by + threadIdx.y + i) * C + bx + threadIdx.x];
    __syncthreads();
    #pragma unroll
    for (int i = 0; i < 32; i += 8)
        out[(size_t)(bx + threadIdx.y + i) * R + by + threadIdx.x] = t[threadIdx.x][threadIdx.y + i];
}

// ---------------------------------------------------------------------------
// c = F_c + timestep_emb(t)[:, :, None]
// ---------------------------------------------------------------------------
__global__ void k_embed_add(const float* __restrict__ F_c,
                            const int*   __restrict__ t,
                            float*       __restrict__ c) {
    int bn = blockIdx.x;
    int b  = bn >> 10;
    int n  = bn & 1023;
    float tv = (float)t[b];
    const float kC = logf(1000.0f) / 511.0f;
    int   i = (n < 512) ? n : (n - 512);
    float f = __expf(-(float)i * kC);
    float e = tv * f;
    float emb = (n < 512) ? sinf(e) : cosf(e);
    size_t base = (size_t)bn * DD_;
    int d = threadIdx.x;
    c[base + d] = F_c[base + d] + emb;
}

// ---------------------------------------------------------------------------
// Warp-per-row softmax over 1024 cols. Block 256 = 8 rows.
// ---------------------------------------------------------------------------
__global__ void k_softmax(float* __restrict__ S) {
    const int wid  = threadIdx.x >> 5;
    const int lane = threadIdx.x & 31;
    float* row = S + ((size_t)blockIdx.x * 8 + wid) * 1024;
    float4 v[8];
    float lmax = -INFINITY;
    #pragma unroll
    for (int j = 0; j < 8; j++) {
        v[j] = *(float4*)(row + j * 128 + lane * 4);
        lmax = fmaxf(lmax, fmaxf(fmaxf(v[j].x, v[j].y), fmaxf(v[j].z, v[j].w)));
    }
    #pragma unroll
    for (int o = 16; o > 0; o >>= 1) lmax = fmaxf(lmax, __shfl_xor_sync(~0u, lmax, o));
    float lsum = 0.0f;
    #pragma unroll
    for (int j = 0; j < 8; j++) {
        v[j].x = __expf(v[j].x - lmax); v[j].y = __expf(v[j].y - lmax);
        v[j].z = __expf(v[j].z - lmax); v[j].w = __expf(v[j].w - lmax);
        lsum += v[j].x + v[j].y + v[j].z + v[j].w;
    }
    #pragma unroll
    for (int o = 16; o > 0; o >>= 1) lsum += __shfl_xor_sync(~0u, lsum, o);
    float inv = 1.0f / lsum;
    #pragma unroll
    for (int j = 0; j < 8; j++) {
        v[j].x *= inv; v[j].y *= inv; v[j].z *= inv; v[j].w *= inv;
        *(float4*)(row + j * 128 + lane * 4) = v[j];
    }
}

// ---------------------------------------------------------------------------
// Row normalize: (x - mean) / (std_ddof1 + 1e-8). One block (128 thr) per row.
// ---------------------------------------------------------------------------
__global__ void k_rownorm(const float* __restrict__ feat,
                          float*       __restrict__ out) {
    int tid = threadIdx.x;
    size_t base = (size_t)blockIdx.x * DD_;
    float x = feat[base + tid];
    __shared__ float red[4];
    float s = x;
    #pragma unroll
    for (int o = 16; o > 0; o >>= 1) s += __shfl_xor_sync(0xffffffffu, s, o);
    if ((tid & 31) == 0) red[tid >> 5] = s;
    __syncthreads();
    float mu = (red[0] + red[1] + red[2] + red[3]) * (1.0f / 128.0f);
    float d = x - mu;
    float ss = d * d;
    #pragma unroll
    for (int o = 16; o > 0; o >>= 1) ss += __shfl_xor_sync(0xffffffffu, ss, o);
    __syncthreads();
    if ((tid & 31) == 0) red[tid >> 5] = ss;
    __syncthreads();
    float var = (red[0] + red[1] + red[2] + red[3]) * (1.0f / 127.0f);
    float inv = 1.0f / (sqrtf(var) + 1e-8f);
    out[base + tid] = d * inv;
}

// ---------------------------------------------------------------------------
extern "C" void kernel_launch(void* const* d_in, const int* in_sizes, int n_in,
                              void* d_out, int out_size) {
    const float* A_t = (const float*)d_in[0];
    const float* F_c = (const float*)d_in[1];
    const int*   t   = (const int*)  d_in[2];
    const float* Wq  = (const float*)d_in[3];
    const float* bq  = (const float*)d_in[4];
    const float* Wk  = (const float*)d_in[5];
    const float* bk  = (const float*)d_in[6];
    const float* Wv  = (const float*)d_in[7];
    const float* bv  = (const float*)d_in[8];
    const float* Wo  = (const float*)d_in[9];
    const float* bo  = (const float*)d_in[10];
    const float* Wg  = (const float*)d_in[11];
    float* out = (float*)d_out;

    float *c, *q, *k, *vt, *s, *ctx, *h, *hwt, *feat, *nrm;
    float *wqT, *wkT, *wvT, *woT, *wgT;
    cudaGetSymbolAddress((void**)&c,    g_c);
    cudaGetSymbolAddress((void**)&q,    g_q);
    cudaGetSymbolAddress((void**)&k,    g_k);
    cudaGetSymbolAddress((void**)&vt,   g_vt);
    cudaGetSymbolAddress((void**)&s,    g_s);
    cudaGetSymbolAddress((void**)&ctx,  g_ctx);
    cudaGetSymbolAddress((void**)&h,    g_h);
    cudaGetSymbolAddress((void**)&hwt,  g_hwt);
    cudaGetSymbolAddress((void**)&feat, g_feat);
    cudaGetSymbolAddress((void**)&nrm,  g_norm);
    cudaGetSymbolAddress((void**)&wqT,  g_wqT);
    cudaGetSymbolAddress((void**)&wkT,  g_wkT);
    cudaGetSymbolAddress((void**)&wvT,  g_wvT);
    cudaGetSymbolAddress((void**)&woT,  g_woT);
    cudaGetSymbolAddress((void**)&wgT,  g_wgT);

    const size_t sBN = (size_t)NN_ * HH_ * DD_;   // 1M
    const size_t sBD = (size_t)NN_ * DD_;         // 128K
    const size_t sNN = (size_t)NN_ * NN_;         // 1M
    const int    HD  = HH_ * DD_;                 // 1024
    const float  scl = 0.08838834764831845f;      // 1/sqrt(128)

    // 0) weight transposes (once per launch, ~1.3 MB)
    {
        dim3 b(32, 8);
        k_transpose<<<dim3(32, 4),  b>>>(Wq, wqT, DD_, HD);    // [128,1024]->[1024,128]
        k_transpose<<<dim3(32, 4),  b>>>(Wk, wkT, DD_, HD);
        k_transpose<<<dim3(32, 4),  b>>>(Wv, wvT, DD_, HD);
        k_transpose<<<dim3(4, 32),  b>>>(Wo, woT, HD, DD_);    // [1024,128]->[128,1024]
        k_transpose<<<dim3(4, 4),   b>>>(Wg, wgT, DD_, DD_);
    }

    // 1) c = F_c + t_emb
    k_embed_add<<<BSZ * NN_, DD_>>>(F_c, t, c);

    // 2) QKV: c[1024,128] @ WxT[1024,128]^T + bias
    {
        dim3 g(8, 8, BSZ);
        gemm_tb<false, true, false><<<g, 256>>>(c, DD_, sBD, 0,
                                                wqT, DD_, 0, 0,
                                                q, HD, sBN, 0,
                                                bq, DD_, 1, 1.0f);
        gemm_tb<false, true, false><<<g, 256>>>(c, DD_, sBD, 0,
                                                wkT, DD_, 0, 0,
                                                k, HD, sBN, 0,
                                                bk, DD_, 1, 1.0f);
        // V written transposed -> vt [b, hd, n]
        gemm_tb<false, true, true><<<g, 256>>>(c, DD_, sBD, 0,
                                               wvT, DD_, 0, 0,
                                               vt, NN_, sBN, 0,
                                               bv, DD_, 1, 1.0f);
    }

    // 3a) scores[b,h] = scl * Q_bh @ K_bh^T   (128 batch-heads)
    {
        dim3 g(8, 8, BSZ * HH_);
        gemm_tb<false, false, false><<<g, 256>>>(q, HD, sBN, DD_,
                                                 k, HD, sBN, DD_,
                                                 s, NN_, (size_t)HH_ * sNN, sNN,
                                                 nullptr, DD_, HH_, scl);
    }
    // 3b) softmax
    k_softmax<<<BSZ * HH_ * NN_ / 8, 256>>>(s);

    // 3c) ctx[b,h] = P_bh @ (V^T_bh)^T   -> ctx [b, n, h*128+d]
    {
        dim3 g(1, 8, BSZ * HH_);
        gemm_tb<false, false, false><<<g, 256>>>(s, NN_, (size_t)HH_ * sNN, sNN,
                                                 vt, NN_, sBN, (size_t)DD_ * NN_,
                                                 ctx, HD, sBN, DD_,
                                                 nullptr, NN_, HH_, 1.0f);
    }

    // 4) h = ctx @ Wo + bo   (B = woT [128,1024])
    {
        dim3 g(1, 8, BSZ);
        gemm_tb<false, true, false><<<g, 256>>>(ctx, HD, sBN, 0,
                                                woT, HD, 0, 0,
                                                h, DD_, sBD, 0,
                                                bo, HD, 1, 1.0f);
    }
    // 5) hw = h @ Wg, written transposed -> hwt [b, d, n]
    {
        dim3 g(1, 8, BSZ);
        gemm_tb<false, false, true><<<g, 256>>>(h, DD_, sBD, 0,
                                                wgT, DD_, 0, 0,
                                                hwt, NN_, sBD, 0,
                                                nullptr, DD_, 1, 1.0f);
    }
    // 6) feat = relu(A_t @ hw)  (B = hwt [128,1024] per batch)
    {
        dim3 g(1, 8, BSZ);
        gemm_tb<true, false, false><<<g, 256>>>(A_t, NN_, sNN, 0,
                                                hwt, NN_, sBD, 0,
                                                feat, DD_, sBD, 0,
                                                nullptr, NN_, 1, 1.0f);
    }
    // 7) row normalize
    k_rownorm<<<BSZ * NN_, DD_>>>(feat, nrm);

    // 8) out = (norm @ norm^T) / 128
    {
        dim3 g(8, 8, BSZ);
        gemm_tb<false, false, false><<<g, 256>>>(nrm, DD_, sBD, 0,
                                                 nrm, DD_, sBD, 0,
                                                 out, NN_, sNN, 0,
                                                 nullptr, DD_, 1, 1.0f / 128.0f);
    }
}

// round 6
// speedup vs baseline: 3.1196x; 1.2801x over previous
#include <cuda_runtime.h>
#include <math.h>
#include <stdint.h>

#define BSZ 16
#define NN_ 1024
#define DD_ 128
#define HH_ 8

// ---------------------------------------------------------------------------
// Static scratch
// ---------------------------------------------------------------------------
__device__ float g_c   [BSZ * NN_ * DD_];
__device__ float g_q   [BSZ * NN_ * HH_ * DD_];      // [b, n, hd]
__device__ float g_k   [BSZ * NN_ * HH_ * DD_];      // [b, n, hd]
__device__ float g_vt  [BSZ * NN_ * HH_ * DD_];      // [b, hd, n]  (V^T)
__device__ float g_ctx [BSZ * NN_ * HH_ * DD_];      // [b, n, hd]
__device__ float g_h   [BSZ * NN_ * DD_];
__device__ float g_hwt [BSZ * NN_ * DD_];            // [b, d, n]  (hw^T)
__device__ float g_feat[BSZ * NN_ * DD_];
__device__ float g_norm[BSZ * NN_ * DD_];
__device__ float g_wqT [NN_ * DD_];
__device__ float g_wkT [NN_ * DD_];
__device__ float g_wvT [NN_ * DD_];
__device__ float g_woT [NN_ * DD_];
__device__ float g_wgT [DD_ * DD_];

// ---------------------------------------------------------------------------
__device__ __forceinline__ uint32_t tf32r(float x) {   // round-to-nearest tf32
    uint32_t u;
    asm("cvt.rna.tf32.f32 %0, %1;" : "=r"(u) : "f"(x));
    return u;
}
__device__ __forceinline__ void mma_tf32(float* d, const uint32_t* a, const uint32_t* b) {
    asm volatile(
        "mma.sync.aligned.m16n8k8.row.col.f32.tf32.tf32.f32 "
        "{%0,%1,%2,%3}, {%4,%5,%6,%7}, {%8,%9}, {%0,%1,%2,%3};"
        : "+f"(d[0]), "+f"(d[1]), "+f"(d[2]), "+f"(d[3])
        : "r"(a[0]), "r"(a[1]), "r"(a[2]), "r"(a[3]), "r"(b[0]), "r"(b[1]));
}
__device__ __forceinline__ uint4 cvt4(float4 v) {
    uint4 u;
    u.x = tf32r(v.x); u.y = tf32r(v.y); u.z = tf32r(v.z); u.w = tf32r(v.w);
    return u;
}

// ---------------------------------------------------------------------------
// Fused flash attention: ctx[b, n, h*128+d] = softmax(scl*Q@K^T) @ V
// CTA = (qt, b*8+h). 256 thr = 8 warps, warp owns 16 q-rows.
// K-tile = 64 positions per iteration (16 iterations over 1024).
// Frag layouts (word granularity, lane = g*4+tig):
//   A-frag [MxK]: word = ((mtile*NKC + kc)*4 + rk*2+rm)*32 + lane
//   B-frag [NxK]: word = ((kc*NT8 + nt8)*2 + rk)*32 + lane
// ---------------------------------------------------------------------------
__global__ void __launch_bounds__(256) k_flash(
    const float* __restrict__ Qg, const float* __restrict__ Kg,
    const float* __restrict__ Vt, float* __restrict__ Cx) {
    extern __shared__ uint32_t dsm[];
    uint32_t* sQ = dsm;            // 16384 words: Q A-frag (128x128, NKC=16)
    uint32_t* sK = dsm + 16384;    //  8192 words: K B-frag (64x128, NT8=8, NKC=16)
    uint32_t* sV = dsm + 24576;    //  8192 words: V^T B-frag (128x64, NT8=16, NKC=8)
    uint32_t* sP = dsm + 32768;    //  8192 words: P A-frag (128x64, NKC=8)

    const int tid = threadIdx.x;
    const int w = tid >> 5, l = tid & 31;
    const int g = l >> 2, tig = l & 3;
    const int gg = l & 7, s = l >> 3;
    const int b = blockIdx.y >> 3, h = blockIdx.y & 7;
    const int qt = blockIdx.x;

    const size_t sBN = (size_t)NN_ * HH_ * DD_;
    const float* qp = Qg + (size_t)b * sBN + (size_t)qt * 128 * 1024 + h * 128;
    const float* kp = Kg + (size_t)b * sBN + h * 128;
    const float* vp = Vt + (size_t)b * sBN + (size_t)(h * 128) * 1024;
    float*       cp = Cx + (size_t)b * sBN + (size_t)qt * 128 * 1024 + h * 128;

    // ---- stage Q (x 1/sqrt(128), tf32) ----
    {
        const int r  = w * 16 + gg + (s & 1) * 8;
        const int rm = s & 1;
        const float* src = qp + (size_t)r * 1024;
        #pragma unroll
        for (int i = 0; i < 16; i++) {
            const int qd = (s >> 1) + i * 2;
            float4 v = *(const float4*)(src + qd * 4);
            const float scl = 0.08838834764831845f;
            v.x *= scl; v.y *= scl; v.z *= scl; v.w *= scl;
            const int kc = qd >> 1, rk = qd & 1;
            const uint32_t base = (uint32_t)((((w * 16 + kc) * 4 + rk * 2 + rm) * 32) + gg * 4);
            *(uint4*)&sQ[base] = cvt4(v);
        }
    }

    float m0 = -INFINITY, m1 = -INFINITY, l0 = 0.0f, l1 = 0.0f;
    float o[16][4];
    #pragma unroll
    for (int nt = 0; nt < 16; nt++)
        #pragma unroll
        for (int r = 0; r < 4; r++) o[nt][r] = 0.0f;

    for (int kt = 0; kt < 16; kt++) {
        __syncthreads();   // prev PV reads of sK/sV done; (iter 0: sQ visible)
        // ---- stage K tile [64 x 128] ----
        {
            const int r2 = w * 8 + gg;
            const float* src = kp + (size_t)(kt * 64 + r2) * 1024;
            #pragma unroll
            for (int i = 0; i < 8; i++) {
                const int qd = s + i * 4;
                float4 v = *(const float4*)(src + qd * 4);
                const uint32_t base =
                    (uint32_t)(((((qd >> 1) * 8 + w) * 2 + (qd & 1)) * 32) + gg * 4);
                *(uint4*)&sK[base] = cvt4(v);
            }
        }
        // ---- stage V^T tile [128 x 64] ----
        {
            const int dd = w * 16 + gg + (s & 1) * 8;
            const int nt8v = dd >> 3;
            const float* src = vp + (size_t)dd * 1024 + kt * 64;
            #pragma unroll
            for (int i = 0; i < 8; i++) {
                const int qd = (s >> 1) + i * 2;
                float4 v = *(const float4*)(src + qd * 4);
                const uint32_t base =
                    (uint32_t)(((((qd >> 1) * 16 + nt8v) * 2 + (qd & 1)) * 32) + gg * 4);
                *(uint4*)&sV[base] = cvt4(v);
            }
        }
        __syncthreads();

        // ---- S = Qs @ K^T  (warp: 16 rows x 64 cols) ----
        float sc[8][4];
        #pragma unroll
        for (int nt = 0; nt < 8; nt++)
            #pragma unroll
            for (int r = 0; r < 4; r++) sc[nt][r] = 0.0f;
        #pragma unroll
        for (int kc = 0; kc < 16; kc++) {
            uint32_t af[4];
            const uint32_t ab = (uint32_t)(((w * 16 + kc) * 4) * 32 + l);
            af[0] = sQ[ab]; af[1] = sQ[ab + 32]; af[2] = sQ[ab + 64]; af[3] = sQ[ab + 96];
            #pragma unroll
            for (int nt = 0; nt < 8; nt++) {
                const uint32_t bb = (uint32_t)(((kc * 8 + nt) * 2) * 32 + l);
                uint32_t bf[2] = {sK[bb], sK[bb + 32]};
                mma_tf32(sc[nt], af, bf);
            }
        }

        // ---- online softmax (rows w*16+g and +8; reduce over tig via shfl) ----
        float tm0 = -INFINITY, tm1 = -INFINITY;
        #pragma unroll
        for (int nt = 0; nt < 8; nt++) {
            tm0 = fmaxf(tm0, fmaxf(sc[nt][0], sc[nt][1]));
            tm1 = fmaxf(tm1, fmaxf(sc[nt][2], sc[nt][3]));
        }
        tm0 = fmaxf(tm0, __shfl_xor_sync(~0u, tm0, 1));
        tm0 = fmaxf(tm0, __shfl_xor_sync(~0u, tm0, 2));
        tm1 = fmaxf(tm1, __shfl_xor_sync(~0u, tm1, 1));
        tm1 = fmaxf(tm1, __shfl_xor_sync(~0u, tm1, 2));
        const float mn0 = fmaxf(m0, tm0), mn1 = fmaxf(m1, tm1);
        const float c0 = __expf(m0 - mn0), c1 = __expf(m1 - mn1);
        m0 = mn0; m1 = mn1;

        float rs0 = 0.0f, rs1 = 0.0f;
        const uint32_t pbase = (uint32_t)(((tig >> 1) * 2) * 32 + g * 4 + (tig & 1) * 2);
        #pragma unroll
        for (int nt = 0; nt < 8; nt++) {
            const float p0 = __expf(sc[nt][0] - mn0);
            const float p1 = __expf(sc[nt][1] - mn0);
            const float p2 = __expf(sc[nt][2] - mn1);
            const float p3 = __expf(sc[nt][3] - mn1);
            rs0 += p0 + p1;
            rs1 += p2 + p3;
            const uint32_t wb = (uint32_t)(((w * 8 + nt) * 4) * 32) + pbase;
            uint2 lo, hi;
            lo.x = tf32r(p0); lo.y = tf32r(p1);
            hi.x = tf32r(p2); hi.y = tf32r(p3);
            *(uint2*)&sP[wb]      = lo;     // rm = 0
            *(uint2*)&sP[wb + 32] = hi;     // rm = 1
        }
        rs0 += __shfl_xor_sync(~0u, rs0, 1);
        rs0 += __shfl_xor_sync(~0u, rs0, 2);
        rs1 += __shfl_xor_sync(~0u, rs1, 1);
        rs1 += __shfl_xor_sync(~0u, rs1, 2);
        l0 = l0 * c0 + rs0;
        l1 = l1 * c1 + rs1;
        #pragma unroll
        for (int nt = 0; nt < 16; nt++) {
            o[nt][0] *= c0; o[nt][1] *= c0;
            o[nt][2] *= c1; o[nt][3] *= c1;
        }
        __syncwarp();      // sP produced+consumed within this warp only

        // ---- O += P @ V  (warp: 16 rows x 128 d) ----
        #pragma unroll
        for (int kc = 0; kc < 8; kc++) {
            uint32_t af[4];
            const uint32_t ab = (uint32_t)(((w * 8 + kc) * 4) * 32 + l);
            af[0] = sP[ab]; af[1] = sP[ab + 32]; af[2] = sP[ab + 64]; af[3] = sP[ab + 96];
            #pragma unroll
            for (int nt = 0; nt < 16; nt++) {
                const uint32_t bb = (uint32_t)(((kc * 16 + nt) * 2) * 32 + l);
                uint32_t bf[2] = {sV[bb], sV[bb + 32]};
                mma_tf32(o[nt], af, bf);
            }
        }
    }

    // ---- finalize ----
    const float i0 = 1.0f / l0, i1 = 1.0f / l1;
    float* r0p = cp + (size_t)(w * 16 + g) * 1024;
    float* r1p = cp + (size_t)(w * 16 + g + 8) * 1024;
    #pragma unroll
    for (int nt = 0; nt < 16; nt++) {
        const int col = nt * 8 + tig * 2;
        *(float2*)(r0p + col) = make_float2(o[nt][0] * i0, o[nt][1] * i0);
        *(float2*)(r1p + col) = make_float2(o[nt][2] * i1, o[nt][3] * i1);
    }
}

// ---------------------------------------------------------------------------
// tf32 GEMM (as round 5): C = alpha * A @ B^T (+bias) (+relu), optional C^T.
// ---------------------------------------------------------------------------
template<bool RELU, bool HASBIAS, bool CT>
__global__ void __launch_bounds__(256)
gemm_tb(const float* __restrict__ A, int lda, size_t aOut, size_t aIn,
        const float* __restrict__ B, int ldb, size_t bOut, size_t bIn,
        float*       __restrict__ C, int ldc, size_t cOut, size_t cIn,
        const float* __restrict__ bias,
        int K, int zInner, float alpha) {
    __shared__ uint32_t sA[2][2048];
    __shared__ uint32_t sB[2][2048];

    const int tid  = threadIdx.x;
    const int wid  = tid >> 5;
    const int lane = tid & 31;
    const int warp_m = wid & 3;
    const int warp_n = wid >> 2;
    const int g   = lane >> 2;
    const int tig = lane & 3;

    int z  = blockIdx.z;
    int zo = z / zInner, zi = z - zo * zInner;
    A += (size_t)zo * aOut + (size_t)zi * aIn;
    B += (size_t)zo * bOut + (size_t)zi * bIn;
    C += (size_t)zo * cOut + (size_t)zi * cIn;

    const int m0 = blockIdx.y * 128, n0 = blockIdx.x * 128;

    const int sw = wid;
    const int qk = lane >> 3;
    const int gg = lane & 7;
    const int rk = qk & 1, kk0 = qk >> 1;

    const uint32_t aSt0 = ((((((sw >> 1) * 2 + kk0) * 2) + (sw & 1)) * 4 + rk * 2) * 32) + gg * 4;
    const uint32_t aSt1 = aSt0 + 32;
    const uint32_t bSt0 = (((((sw >> 2) * 2 + kk0) * 8 + ((sw * 2) & 7)) * 2 + rk) * 32) + gg * 4;
    const uint32_t bSt1 = bSt0 + 64;

    const float* Ap = A + (size_t)(m0 + sw * 16 + gg) * lda + qk * 4;
    const float* Bp = B + (size_t)(n0 + sw * 16 + gg) * ldb + qk * 4;
    const size_t a8 = (size_t)8 * lda, b8 = (size_t)8 * ldb;

    float acc[2][8][4];
    #pragma unroll
    for (int mt = 0; mt < 2; mt++)
        #pragma unroll
        for (int nt = 0; nt < 8; nt++)
            #pragma unroll
            for (int r = 0; r < 4; r++) acc[mt][nt][r] = 0.0f;

    float4 ra0, ra1, rb0, rb1;
    ra0 = *(const float4*)(Ap);
    ra1 = *(const float4*)(Ap + a8);
    rb0 = *(const float4*)(Bp);
    rb1 = *(const float4*)(Bp + b8);
    *(uint4*)&sA[0][aSt0] = cvt4(ra0);
    *(uint4*)&sA[0][aSt1] = cvt4(ra1);
    *(uint4*)&sB[0][bSt0] = cvt4(rb0);
    *(uint4*)&sB[0][bSt1] = cvt4(rb1);
    __syncthreads();

    const int nkt = K >> 4;
    for (int kt = 0; kt < nkt; kt++) {
        const int cur = kt & 1;
        if (kt + 1 < nkt) {
            const int k0 = (kt + 1) << 4;
            ra0 = *(const float4*)(Ap + k0);
            ra1 = *(const float4*)(Ap + k0 + a8);
            rb0 = *(const float4*)(Bp + k0);
            rb1 = *(const float4*)(Bp + k0 + b8);
        }
        const uint32_t* aB = sA[cur];
        const uint32_t* bB = sB[cur];
        #pragma unroll
        for (int kk = 0; kk < 2; kk++) {
            uint32_t af[2][4];
            #pragma unroll
            for (int mt = 0; mt < 2; mt++) {
                const uint32_t base = (((warp_m * 2 + kk) * 2 + mt) * 4) * 32 + lane;
                af[mt][0] = aB[base];
                af[mt][1] = aB[base + 32];
                af[mt][2] = aB[base + 64];
                af[mt][3] = aB[base + 96];
            }
            uint32_t bf[8][2];
            #pragma unroll
            for (int nt = 0; nt < 8; nt++) {
                const uint32_t base = ((((warp_n * 2 + kk) * 8 + nt) * 2) * 32) + lane;
                bf[nt][0] = bB[base];
                bf[nt][1] = bB[base + 32];
            }
            #pragma unroll
            for (int mt = 0; mt < 2; mt++)
                #pragma unroll
                for (int nt = 0; nt < 8; nt++)
                    mma_tf32(acc[mt][nt], af[mt], bf[nt]);
        }
        if (kt + 1 < nkt) {
            const int nxt = cur ^ 1;
            __syncthreads();
            *(uint4*)&sA[nxt][aSt0] = cvt4(ra0);
            *(uint4*)&sA[nxt][aSt1] = cvt4(ra1);
            *(uint4*)&sB[nxt][bSt0] = cvt4(rb0);
            *(uint4*)&sB[nxt][bSt1] = cvt4(rb1);
            __syncthreads();
        }
    }

    #pragma unroll
    for (int mt = 0; mt < 2; mt++) {
        const int row = m0 + warp_m * 32 + mt * 16 + g;
        #pragma unroll
        for (int nt = 0; nt < 8; nt++) {
            const int col = n0 + warp_n * 64 + nt * 8 + tig * 2;
            float v0 = acc[mt][nt][0] * alpha;
            float v1 = acc[mt][nt][1] * alpha;
            float v2 = acc[mt][nt][2] * alpha;
            float v3 = acc[mt][nt][3] * alpha;
            if (HASBIAS) {
                float b0 = bias[col], b1 = bias[col + 1];
                v0 += b0; v1 += b1; v2 += b0; v3 += b1;
            }
            if (RELU) {
                v0 = fmaxf(v0, 0.0f); v1 = fmaxf(v1, 0.0f);
                v2 = fmaxf(v2, 0.0f); v3 = fmaxf(v3, 0.0f);
            }
            if (CT) {
                C[(size_t)col * ldc + row]           = v0;
                C[(size_t)(col + 1) * ldc + row]     = v1;
                C[(size_t)col * ldc + row + 8]       = v2;
                C[(size_t)(col + 1) * ldc + row + 8] = v3;
            } else {
                *(float2*)(C + (size_t)row * ldc + col)       = make_float2(v0, v1);
                *(float2*)(C + (size_t)(row + 8) * ldc + col) = make_float2(v2, v3);
            }
        }
    }
}

// ---------------------------------------------------------------------------
__global__ void k_transpose(const float* __restrict__ in, float* __restrict__ out,
                            int R, int C) {
    __shared__ float t[32][33];
    int bx = blockIdx.x * 32, by = blockIdx.y * 32;
    #pragma unroll
    for (int i = 0; i < 32; i += 8)
        t[threadIdx.y + i][threadIdx.x] = in[(size_t)(by + threadIdx.y + i) * C + bx + threadIdx.x];
    __syncthreads();
    #pragma unroll
    for (int i = 0; i < 32; i += 8)
        out[(size_t)(bx + threadIdx.y + i) * R + by + threadIdx.x] = t[threadIdx.x][threadIdx.y + i];
}

// ---------------------------------------------------------------------------
__global__ void k_embed_add(const float* __restrict__ F_c,
                            const int*   __restrict__ t,
                            float*       __restrict__ c) {
    int bn = blockIdx.x;
    int b  = bn >> 10;
    int n  = bn & 1023;
    float tv = (float)t[b];
    const float kC = logf(1000.0f) / 511.0f;
    int   i = (n < 512) ? n : (n - 512);
    float f = __expf(-(float)i * kC);
    float e = tv * f;
    float emb = (n < 512) ? sinf(e) : cosf(e);
    size_t base = (size_t)bn * DD_;
    int d = threadIdx.x;
    c[base + d] = F_c[base + d] + emb;
}

// ---------------------------------------------------------------------------
__global__ void k_rownorm(const float* __restrict__ feat,
                          float*       __restrict__ out) {
    int tid = threadIdx.x;
    size_t base = (size_t)blockIdx.x * DD_;
    float x = feat[base + tid];
    __shared__ float red[4];
    float s = x;
    #pragma unroll
    for (int o = 16; o > 0; o >>= 1) s += __shfl_xor_sync(0xffffffffu, s, o);
    if ((tid & 31) == 0) red[tid >> 5] = s;
    __syncthreads();
    float mu = (red[0] + red[1] + red[2] + red[3]) * (1.0f / 128.0f);
    float d = x - mu;
    float ss = d * d;
    #pragma unroll
    for (int o = 16; o > 0; o >>= 1) ss += __shfl_xor_sync(0xffffffffu, ss, o);
    __syncthreads();
    if ((tid & 31) == 0) red[tid >> 5] = ss;
    __syncthreads();
    float var = (red[0] + red[1] + red[2] + red[3]) * (1.0f / 127.0f);
    float inv = 1.0f / (sqrtf(var) + 1e-8f);
    out[base + tid] = d * inv;
}

// ---------------------------------------------------------------------------
extern "C" void kernel_launch(void* const* d_in, const int* in_sizes, int n_in,
                              void* d_out, int out_size) {
    const float* A_t = (const float*)d_in[0];
    const float* F_c = (const float*)d_in[1];
    const int*   t   = (const int*)  d_in[2];
    const float* Wq  = (const float*)d_in[3];
    const float* bq  = (const float*)d_in[4];
    const float* Wk  = (const float*)d_in[5];
    const float* bk  = (const float*)d_in[6];
    const float* Wv  = (const float*)d_in[7];
    const float* bv  = (const float*)d_in[8];
    const float* Wo  = (const float*)d_in[9];
    const float* bo  = (const float*)d_in[10];
    const float* Wg  = (const float*)d_in[11];
    float* out = (float*)d_out;

    float *c, *q, *k, *vt, *ctx, *h, *hwt, *feat, *nrm;
    float *wqT, *wkT, *wvT, *woT, *wgT;
    cudaGetSymbolAddress((void**)&c,    g_c);
    cudaGetSymbolAddress((void**)&q,    g_q);
    cudaGetSymbolAddress((void**)&k,    g_k);
    cudaGetSymbolAddress((void**)&vt,   g_vt);
    cudaGetSymbolAddress((void**)&ctx,  g_ctx);
    cudaGetSymbolAddress((void**)&h,    g_h);
    cudaGetSymbolAddress((void**)&hwt,  g_hwt);
    cudaGetSymbolAddress((void**)&feat, g_feat);
    cudaGetSymbolAddress((void**)&nrm,  g_norm);
    cudaGetSymbolAddress((void**)&wqT,  g_wqT);
    cudaGetSymbolAddress((void**)&wkT,  g_wkT);
    cudaGetSymbolAddress((void**)&wvT,  g_wvT);
    cudaGetSymbolAddress((void**)&woT,  g_woT);
    cudaGetSymbolAddress((void**)&wgT,  g_wgT);

    const size_t sBN = (size_t)NN_ * HH_ * DD_;
    const size_t sBD = (size_t)NN_ * DD_;
    const size_t sNN = (size_t)NN_ * NN_;
    const int    HD  = HH_ * DD_;

    // flash kernel smem opt-in (163840 B)
    cudaFuncSetAttribute(k_flash, cudaFuncAttributeMaxDynamicSharedMemorySize, 163840);

    // 0) weight transposes
    {
        dim3 b(32, 8);
        k_transpose<<<dim3(32, 4), b>>>(Wq, wqT, DD_, HD);
        k_transpose<<<dim3(32, 4), b>>>(Wk, wkT, DD_, HD);
        k_transpose<<<dim3(32, 4), b>>>(Wv, wvT, DD_, HD);
        k_transpose<<<dim3(4, 32), b>>>(Wo, woT, HD, DD_);
        k_transpose<<<dim3(4, 4),  b>>>(Wg, wgT, DD_, DD_);
    }

    // 1) c = F_c + t_emb
    k_embed_add<<<BSZ * NN_, DD_>>>(F_c, t, c);

    // 2) QKV
    {
        dim3 g(8, 8, BSZ);
        gemm_tb<false, true, false><<<g, 256>>>(c, DD_, sBD, 0,
                                                wqT, DD_, 0, 0,
                                                q, HD, sBN, 0,
                                                bq, DD_, 1, 1.0f);
        gemm_tb<false, true, false><<<g, 256>>>(c, DD_, sBD, 0,
                                                wkT, DD_, 0, 0,
                                                k, HD, sBN, 0,
                                                bk, DD_, 1, 1.0f);
        gemm_tb<false, true, true><<<g, 256>>>(c, DD_, sBD, 0,
                                               wvT, DD_, 0, 0,
                                               vt, NN_, sBN, 0,
                                               bv, DD_, 1, 1.0f);
    }

    // 3) fused attention
    k_flash<<<dim3(8, BSZ * HH_), 256, 163840>>>(q, k, vt, ctx);

    // 4) h = ctx @ Wo + bo
    {
        dim3 g(1, 8, BSZ);
        gemm_tb<false, true, false><<<g, 256>>>(ctx, HD, sBN, 0,
                                                woT, HD, 0, 0,
                                                h, DD_, sBD, 0,
                                                bo, HD, 1, 1.0f);
    }
    // 5) hw = h @ Wg (transposed out)
    {
        dim3 g(1, 8, BSZ);
        gemm_tb<false, false, true><<<g, 256>>>(h, DD_, sBD, 0,
                                                wgT, DD_, 0, 0,
                                                hwt, NN_, sBD, 0,
                                                nullptr, DD_, 1, 1.0f);
    }
    // 6) feat = relu(A_t @ hw)
    {
        dim3 g(1, 8, BSZ);
        gemm_tb<true, false, false><<<g, 256>>>(A_t, NN_, sNN, 0,
                                                hwt, NN_, sBD, 0,
                                                feat, DD_, sBD, 0,
                                                nullptr, NN_, 1, 1.0f);
    }
    // 7) row normalize
    k_rownorm<<<BSZ * NN_, DD_>>>(feat, nrm);

    // 8) out = (norm @ norm^T) / 128
    {
        dim3 g(8, 8, BSZ);
        gemm_tb<false, false, false><<<g, 256>>>(nrm, DD_, sBD, 0,
                                                 nrm, DD_, sBD, 0,
                                                 out, NN_, sNN, 0,
                                                 nullptr, DD_, 1, 1.0f / 128.0f);
    }
}

// round 7
// speedup vs baseline: 3.1744x; 1.0176x over previous
#include <cuda_runtime.h>
#include <math.h>
#include <stdint.h>

#define BSZ 16
#define NN_ 1024
#define DD_ 128
#define HH_ 8

// ---------------------------------------------------------------------------
// Static scratch
// ---------------------------------------------------------------------------
__device__ float g_c   [BSZ * NN_ * DD_];
__device__ float g_q   [BSZ * NN_ * HH_ * DD_];      // [b, n, hd]
__device__ float g_k   [BSZ * NN_ * HH_ * DD_];      // [b, n, hd]
__device__ float g_vt  [BSZ * NN_ * HH_ * DD_];      // [b, hd, n]  (V^T)
__device__ float g_ctx [BSZ * NN_ * HH_ * DD_];      // [b, n, hd]
__device__ float g_h   [BSZ * NN_ * DD_];
__device__ float g_hwt [BSZ * NN_ * DD_];            // [b, d, n]  (hw^T)
__device__ float g_feat[BSZ * NN_ * DD_];
__device__ float g_norm[BSZ * NN_ * DD_];
__device__ float g_wqT [NN_ * DD_];
__device__ float g_wkT [NN_ * DD_];
__device__ float g_wvT [NN_ * DD_];
__device__ float g_woT [NN_ * DD_];
__device__ float g_wgT [DD_ * DD_];

// ---------------------------------------------------------------------------
__device__ __forceinline__ uint32_t tf32r(float x) {   // round-to-nearest tf32
    uint32_t u;
    asm("cvt.rna.tf32.f32 %0, %1;" : "=r"(u) : "f"(x));
    return u;
}
__device__ __forceinline__ void mma_tf32(float* d, const uint32_t* a, const uint32_t* b) {
    asm volatile(
        "mma.sync.aligned.m16n8k8.row.col.f32.tf32.tf32.f32 "
        "{%0,%1,%2,%3}, {%4,%5,%6,%7}, {%8,%9}, {%0,%1,%2,%3};"
        : "+f"(d[0]), "+f"(d[1]), "+f"(d[2]), "+f"(d[3])
        : "r"(a[0]), "r"(a[1]), "r"(a[2]), "r"(a[3]), "r"(b[0]), "r"(b[1]));
}
__device__ __forceinline__ uint4 cvt4(float4 v) {
    uint4 u;
    u.x = tf32r(v.x); u.y = tf32r(v.y); u.z = tf32r(v.z); u.w = tf32r(v.w);
    return u;
}

// ---------------------------------------------------------------------------
// Fused flash attention, register-prefetch pipelined.
// ctx[b, n, h*128+d] = softmax(scl*Q@K^T) @ V
// CTA = (qt, b*8+h). 256 thr = 8 warps, warp owns 16 q-rows.
// K-tile = 64 positions per iteration (16 iterations over 1024).
// ---------------------------------------------------------------------------
__global__ void __launch_bounds__(256) k_flash(
    const float* __restrict__ Qg, const float* __restrict__ Kg,
    const float* __restrict__ Vt, float* __restrict__ Cx) {
    extern __shared__ uint32_t dsm[];
    uint32_t* sQ = dsm;            // 16384 words: Q A-frag (128x128, NKC=16)
    uint32_t* sK = dsm + 16384;    //  8192 words: K B-frag (64x128)
    uint32_t* sV = dsm + 24576;    //  8192 words: V^T B-frag (128x64)
    uint32_t* sP = dsm + 32768;    //  8192 words: P A-frag (128x64)

    const int tid = threadIdx.x;
    const int w = tid >> 5, l = tid & 31;
    const int g = l >> 2, tig = l & 3;
    const int gg = l & 7, s = l >> 3;
    const int b = blockIdx.y >> 3, h = blockIdx.y & 7;
    const int qt = blockIdx.x;

    const size_t sBN = (size_t)NN_ * HH_ * DD_;
    const float* qp = Qg + (size_t)b * sBN + (size_t)qt * 128 * 1024 + h * 128;
    const float* kp = Kg + (size_t)b * sBN + h * 128;
    const float* vp = Vt + (size_t)b * sBN + (size_t)(h * 128) * 1024;
    float*       cp = Cx + (size_t)b * sBN + (size_t)qt * 128 * 1024 + h * 128;

    // ---- stage Q (x 1/sqrt(128), tf32) ----
    {
        const int r  = w * 16 + gg + (s & 1) * 8;
        const int rm = s & 1;
        const float* src = qp + (size_t)r * 1024;
        #pragma unroll
        for (int i = 0; i < 16; i++) {
            const int qd = (s >> 1) + i * 2;
            float4 v = *(const float4*)(src + qd * 4);
            const float scl = 0.08838834764831845f;
            v.x *= scl; v.y *= scl; v.z *= scl; v.w *= scl;
            const int kc = qd >> 1, rk = qd & 1;
            const uint32_t base = (uint32_t)((((w * 16 + kc) * 4 + rk * 2 + rm) * 32) + gg * 4);
            *(uint4*)&sQ[base] = cvt4(v);
        }
    }

    // ---- prefetch addressing (constant per thread) ----
    // K: row w*8+gg of the 64-row tile, quads qd = s + i*4
    const float* kRow = kp + (size_t)(w * 8 + gg) * 1024;
    // V: d-row w*16+gg+(s&1)*8, quads qd = (s>>1) + i*2
    const int vdd = w * 16 + gg + (s & 1) * 8;
    const float* vRow = vp + (size_t)vdd * 1024;

    float4 rK[8], rV[8];
    // prologue: load tile 0
    #pragma unroll
    for (int i = 0; i < 8; i++) {
        rK[i] = *(const float4*)(kRow + (s + i * 4) * 4);
        rV[i] = *(const float4*)(vRow + ((s >> 1) + i * 2) * 4);
    }

    float m0 = -INFINITY, m1 = -INFINITY, l0 = 0.0f, l1 = 0.0f;
    float o[16][4];
    #pragma unroll
    for (int nt = 0; nt < 16; nt++)
        #pragma unroll
        for (int r = 0; r < 4; r++) o[nt][r] = 0.0f;

    for (int kt = 0; kt < 16; kt++) {
        __syncthreads();   // prev PV reads of sK/sV done; iter0: sQ staged
        // ---- STS K tile from regs ----
        #pragma unroll
        for (int i = 0; i < 8; i++) {
            const int qd = s + i * 4;
            const uint32_t base =
                (uint32_t)(((((qd >> 1) * 8 + w) * 2 + (qd & 1)) * 32) + gg * 4);
            *(uint4*)&sK[base] = cvt4(rK[i]);
        }
        // ---- STS V tile from regs ----
        #pragma unroll
        for (int i = 0; i < 8; i++) {
            const int qd = (s >> 1) + i * 2;
            const uint32_t base =
                (uint32_t)(((((qd >> 1) * 16 + (vdd >> 3)) * 2 + (qd & 1)) * 32) + gg * 4);
            *(uint4*)&sV[base] = cvt4(rV[i]);
        }
        __syncthreads();

        // ---- issue next tile's global loads (overlap with mma below) ----
        if (kt + 1 < 16) {
            const float* kn = kRow + (size_t)(kt + 1) * 64 * 1024;
            const float* vn = vRow + (kt + 1) * 64;
            #pragma unroll
            for (int i = 0; i < 8; i++) {
                rK[i] = *(const float4*)(kn + (s + i * 4) * 4);
                rV[i] = *(const float4*)(vn + ((s >> 1) + i * 2) * 4);
            }
        }

        // ---- S = Qs @ K^T  (warp: 16 rows x 64 cols) ----
        float sc[8][4];
        #pragma unroll
        for (int nt = 0; nt < 8; nt++)
            #pragma unroll
            for (int r = 0; r < 4; r++) sc[nt][r] = 0.0f;
        #pragma unroll
        for (int kc = 0; kc < 16; kc++) {
            uint32_t af[4];
            const uint32_t ab = (uint32_t)(((w * 16 + kc) * 4) * 32 + l);
            af[0] = sQ[ab]; af[1] = sQ[ab + 32]; af[2] = sQ[ab + 64]; af[3] = sQ[ab + 96];
            #pragma unroll
            for (int nt = 0; nt < 8; nt++) {
                const uint32_t bb = (uint32_t)(((kc * 8 + nt) * 2) * 32 + l);
                uint32_t bf[2] = {sK[bb], sK[bb + 32]};
                mma_tf32(sc[nt], af, bf);
            }
        }

        // ---- online softmax (rows w*16+g and +8; reduce over tig via shfl) ----
        float tm0 = -INFINITY, tm1 = -INFINITY;
        #pragma unroll
        for (int nt = 0; nt < 8; nt++) {
            tm0 = fmaxf(tm0, fmaxf(sc[nt][0], sc[nt][1]));
            tm1 = fmaxf(tm1, fmaxf(sc[nt][2], sc[nt][3]));
        }
        tm0 = fmaxf(tm0, __shfl_xor_sync(~0u, tm0, 1));
        tm0 = fmaxf(tm0, __shfl_xor_sync(~0u, tm0, 2));
        tm1 = fmaxf(tm1, __shfl_xor_sync(~0u, tm1, 1));
        tm1 = fmaxf(tm1, __shfl_xor_sync(~0u, tm1, 2));
        const float mn0 = fmaxf(m0, tm0), mn1 = fmaxf(m1, tm1);
        const float c0 = __expf(m0 - mn0), c1 = __expf(m1 - mn1);
        m0 = mn0; m1 = mn1;

        float rs0 = 0.0f, rs1 = 0.0f;
        const uint32_t pbase = (uint32_t)(((tig >> 1) * 2) * 32 + g * 4 + (tig & 1) * 2);
        #pragma unroll
        for (int nt = 0; nt < 8; nt++) {
            const float p0 = __expf(sc[nt][0] - mn0);
            const float p1 = __expf(sc[nt][1] - mn0);
            const float p2 = __expf(sc[nt][2] - mn1);
            const float p3 = __expf(sc[nt][3] - mn1);
            rs0 += p0 + p1;
            rs1 += p2 + p3;
            const uint32_t wb = (uint32_t)(((w * 8 + nt) * 4) * 32) + pbase;
            uint2 lo, hi;
            lo.x = tf32r(p0); lo.y = tf32r(p1);
            hi.x = tf32r(p2); hi.y = tf32r(p3);
            *(uint2*)&sP[wb]      = lo;     // rm = 0
            *(uint2*)&sP[wb + 32] = hi;     // rm = 1
        }
        rs0 += __shfl_xor_sync(~0u, rs0, 1);
        rs0 += __shfl_xor_sync(~0u, rs0, 2);
        rs1 += __shfl_xor_sync(~0u, rs1, 1);
        rs1 += __shfl_xor_sync(~0u, rs1, 2);
        l0 = l0 * c0 + rs0;
        l1 = l1 * c1 + rs1;
        #pragma unroll
        for (int nt = 0; nt < 16; nt++) {
            o[nt][0] *= c0; o[nt][1] *= c0;
            o[nt][2] *= c1; o[nt][3] *= c1;
        }
        __syncwarp();      // sP produced+consumed within this warp only

        // ---- O += P @ V  (warp: 16 rows x 128 d) ----
        #pragma unroll
        for (int kc = 0; kc < 8; kc++) {
            uint32_t af[4];
            const uint32_t ab = (uint32_t)(((w * 8 + kc) * 4) * 32 + l);
            af[0] = sP[ab]; af[1] = sP[ab + 32]; af[2] = sP[ab + 64]; af[3] = sP[ab + 96];
            #pragma unroll
            for (int nt = 0; nt < 16; nt++) {
                const uint32_t bb = (uint32_t)(((kc * 16 + nt) * 2) * 32 + l);
                uint32_t bf[2] = {sV[bb], sV[bb + 32]};
                mma_tf32(o[nt], af, bf);
            }
        }
    }

    // ---- finalize ----
    const float i0 = 1.0f / l0, i1 = 1.0f / l1;
    float* r0p = cp + (size_t)(w * 16 + g) * 1024;
    float* r1p = cp + (size_t)(w * 16 + g + 8) * 1024;
    #pragma unroll
    for (int nt = 0; nt < 16; nt++) {
        const int col = nt * 8 + tig * 2;
        *(float2*)(r0p + col) = make_float2(o[nt][0] * i0, o[nt][1] * i0);
        *(float2*)(r1p + col) = make_float2(o[nt][2] * i1, o[nt][3] * i1);
    }
}

// ---------------------------------------------------------------------------
// tf32 GEMM: C = alpha * A @ B^T (+bias) (+relu), optional C^T out.
// ---------------------------------------------------------------------------
template<bool RELU, bool HASBIAS, bool CT>
__global__ void __launch_bounds__(256)
gemm_tb(const float* __restrict__ A, int lda, size_t aOut, size_t aIn,
        const float* __restrict__ B, int ldb, size_t bOut, size_t bIn,
        float*       __restrict__ C, int ldc, size_t cOut, size_t cIn,
        const float* __restrict__ bias,
        int K, int zInner, float alpha) {
    __shared__ uint32_t sA[2][2048];
    __shared__ uint32_t sB[2][2048];

    const int tid  = threadIdx.x;
    const int wid  = tid >> 5;
    const int lane = tid & 31;
    const int warp_m = wid & 3;
    const int warp_n = wid >> 2;
    const int g   = lane >> 2;
    const int tig = lane & 3;

    int z  = blockIdx.z;
    int zo = z / zInner, zi = z - zo * zInner;
    A += (size_t)zo * aOut + (size_t)zi * aIn;
    B += (size_t)zo * bOut + (size_t)zi * bIn;
    C += (size_t)zo * cOut + (size_t)zi * cIn;

    const int m0 = blockIdx.y * 128, n0 = blockIdx.x * 128;

    const int sw = wid;
    const int qk = lane >> 3;
    const int gg = lane & 7;
    const int rk = qk & 1, kk0 = qk >> 1;

    const uint32_t aSt0 = ((((((sw >> 1) * 2 + kk0) * 2) + (sw & 1)) * 4 + rk * 2) * 32) + gg * 4;
    const uint32_t aSt1 = aSt0 + 32;
    const uint32_t bSt0 = (((((sw >> 2) * 2 + kk0) * 8 + ((sw * 2) & 7)) * 2 + rk) * 32) + gg * 4;
    const uint32_t bSt1 = bSt0 + 64;

    const float* Ap = A + (size_t)(m0 + sw * 16 + gg) * lda + qk * 4;
    const float* Bp = B + (size_t)(n0 + sw * 16 + gg) * ldb + qk * 4;
    const size_t a8 = (size_t)8 * lda, b8 = (size_t)8 * ldb;

    float acc[2][8][4];
    #pragma unroll
    for (int mt = 0; mt < 2; mt++)
        #pragma unroll
        for (int nt = 0; nt < 8; nt++)
            #pragma unroll
            for (int r = 0; r < 4; r++) acc[mt][nt][r] = 0.0f;

    float4 ra0, ra1, rb0, rb1;
    ra0 = *(const float4*)(Ap);
    ra1 = *(const float4*)(Ap + a8);
    rb0 = *(const float4*)(Bp);
    rb1 = *(const float4*)(Bp + b8);
    *(uint4*)&sA[0][aSt0] = cvt4(ra0);
    *(uint4*)&sA[0][aSt1] = cvt4(ra1);
    *(uint4*)&sB[0][bSt0] = cvt4(rb0);
    *(uint4*)&sB[0][bSt1] = cvt4(rb1);
    __syncthreads();

    const int nkt = K >> 4;
    for (int kt = 0; kt < nkt; kt++) {
        const int cur = kt & 1;
        if (kt + 1 < nkt) {
            const int k0 = (kt + 1) << 4;
            ra0 = *(const float4*)(Ap + k0);
            ra1 = *(const float4*)(Ap + k0 + a8);
            rb0 = *(const float4*)(Bp + k0);
            rb1 = *(const float4*)(Bp + k0 + b8);
        }
        const uint32_t* aB = sA[cur];
        const uint32_t* bB = sB[cur];
        #pragma unroll
        for (int kk = 0; kk < 2; kk++) {
            uint32_t af[2][4];
            #pragma unroll
            for (int mt = 0; mt < 2; mt++) {
                const uint32_t base = (((warp_m * 2 + kk) * 2 + mt) * 4) * 32 + lane;
                af[mt][0] = aB[base];
                af[mt][1] = aB[base + 32];
                af[mt][2] = aB[base + 64];
                af[mt][3] = aB[base + 96];
            }
            uint32_t bf[8][2];
            #pragma unroll
            for (int nt = 0; nt < 8; nt++) {
                const uint32_t base = ((((warp_n * 2 + kk) * 8 + nt) * 2) * 32) + lane;
                bf[nt][0] = bB[base];
                bf[nt][1] = bB[base + 32];
            }
            #pragma unroll
            for (int mt = 0; mt < 2; mt++)
                #pragma unroll
                for (int nt = 0; nt < 8; nt++)
                    mma_tf32(acc[mt][nt], af[mt], bf[nt]);
        }
        if (kt + 1 < nkt) {
            const int nxt = cur ^ 1;
            __syncthreads();
            *(uint4*)&sA[nxt][aSt0] = cvt4(ra0);
            *(uint4*)&sA[nxt][aSt1] = cvt4(ra1);
            *(uint4*)&sB[nxt][bSt0] = cvt4(rb0);
            *(uint4*)&sB[nxt][bSt1] = cvt4(rb1);
            __syncthreads();
        }
    }

    #pragma unroll
    for (int mt = 0; mt < 2; mt++) {
        const int row = m0 + warp_m * 32 + mt * 16 + g;
        #pragma unroll
        for (int nt = 0; nt < 8; nt++) {
            const int col = n0 + warp_n * 64 + nt * 8 + tig * 2;
            float v0 = acc[mt][nt][0] * alpha;
            float v1 = acc[mt][nt][1] * alpha;
            float v2 = acc[mt][nt][2] * alpha;
            float v3 = acc[mt][nt][3] * alpha;
            if (HASBIAS) {
                float b0 = bias[col], b1 = bias[col + 1];
                v0 += b0; v1 += b1; v2 += b0; v3 += b1;
            }
            if (RELU) {
                v0 = fmaxf(v0, 0.0f); v1 = fmaxf(v1, 0.0f);
                v2 = fmaxf(v2, 0.0f); v3 = fmaxf(v3, 0.0f);
            }
            if (CT) {
                C[(size_t)col * ldc + row]           = v0;
                C[(size_t)(col + 1) * ldc + row]     = v1;
                C[(size_t)col * ldc + row + 8]       = v2;
                C[(size_t)(col + 1) * ldc + row + 8] = v3;
            } else {
                *(float2*)(C + (size_t)row * ldc + col)       = make_float2(v0, v1);
                *(float2*)(C + (size_t)(row + 8) * ldc + col) = make_float2(v2, v3);
            }
        }
    }
}

// ---------------------------------------------------------------------------
__global__ void k_transpose(const float* __restrict__ in, float* __restrict__ out,
                            int R, int C) {
    __shared__ float t[32][33];
    int bx = blockIdx.x * 32, by = blockIdx.y * 32;
    #pragma unroll
    for (int i = 0; i < 32; i += 8)
        t[threadIdx.y + i][threadIdx.x] = in[(size_t)(by + threadIdx.y + i) * C + bx + threadIdx.x];
    __syncthreads();
    #pragma unroll
    for (int i = 0; i < 32; i += 8)
        out[(size_t)(bx + threadIdx.y + i) * R + by + threadIdx.x] = t[threadIdx.x][threadIdx.y + i];
}

// ---------------------------------------------------------------------------
__global__ void k_embed_add(const float* __restrict__ F_c,
                            const int*   __restrict__ t,
                            float*       __restrict__ c) {
    int bn = blockIdx.x;
    int b  = bn >> 10;
    int n  = bn & 1023;
    float tv = (float)t[b];
    const float kC = logf(1000.0f) / 511.0f;
    int   i = (n < 512) ? n : (n - 512);
    float f = __expf(-(float)i * kC);
    float e = tv * f;
    float emb = (n < 512) ? sinf(e) : cosf(e);
    size_t base = (size_t)bn * DD_;
    int d = threadIdx.x;
    c[base + d] = F_c[base + d] + emb;
}

// ---------------------------------------------------------------------------
__global__ void k_rownorm(const float* __restrict__ feat,
                          float*       __restrict__ out) {
    int tid = threadIdx.x;
    size_t base = (size_t)blockIdx.x * DD_;
    float x = feat[base + tid];
    __shared__ float red[4];
    float s = x;
    #pragma unroll
    for (int o = 16; o > 0; o >>= 1) s += __shfl_xor_sync(0xffffffffu, s, o);
    if ((tid & 31) == 0) red[tid >> 5] = s;
    __syncthreads();
    float mu = (red[0] + red[1] + red[2] + red[3]) * (1.0f / 128.0f);
    float d = x - mu;
    float ss = d * d;
    #pragma unroll
    for (int o = 16; o > 0; o >>= 1) ss += __shfl_xor_sync(0xffffffffu, ss, o);
    __syncthreads();
    if ((tid & 31) == 0) red[tid >> 5] = ss;
    __syncthreads();
    float var = (red[0] + red[1] + red[2] + red[3]) * (1.0f / 127.0f);
    float inv = 1.0f / (sqrtf(var) + 1e-8f);
    out[base + tid] = d * inv;
}

// ---------------------------------------------------------------------------
extern "C" void kernel_launch(void* const* d_in, const int* in_sizes, int n_in,
                              void* d_out, int out_size) {
    const float* A_t = (const float*)d_in[0];
    const float* F_c = (const float*)d_in[1];
    const int*   t   = (const int*)  d_in[2];
    const float* Wq  = (const float*)d_in[3];
    const float* bq  = (const float*)d_in[4];
    const float* Wk  = (const float*)d_in[5];
    const float* bk  = (const float*)d_in[6];
    const float* Wv  = (const float*)d_in[7];
    const float* bv  = (const float*)d_in[8];
    const float* Wo  = (const float*)d_in[9];
    const float* bo  = (const float*)d_in[10];
    const float* Wg  = (const float*)d_in[11];
    float* out = (float*)d_out;

    float *c, *q, *k, *vt, *ctx, *h, *hwt, *feat, *nrm;
    float *wqT, *wkT, *wvT, *woT, *wgT;
    cudaGetSymbolAddress((void**)&c,    g_c);
    cudaGetSymbolAddress((void**)&q,    g_q);
    cudaGetSymbolAddress((void**)&k,    g_k);
    cudaGetSymbolAddress((void**)&vt,   g_vt);
    cudaGetSymbolAddress((void**)&ctx,  g_ctx);
    cudaGetSymbolAddress((void**)&h,    g_h);
    cudaGetSymbolAddress((void**)&hwt,  g_hwt);
    cudaGetSymbolAddress((void**)&feat, g_feat);
    cudaGetSymbolAddress((void**)&nrm,  g_norm);
    cudaGetSymbolAddress((void**)&wqT,  g_wqT);
    cudaGetSymbolAddress((void**)&wkT,  g_wkT);
    cudaGetSymbolAddress((void**)&wvT,  g_wvT);
    cudaGetSymbolAddress((void**)&woT,  g_woT);
    cudaGetSymbolAddress((void**)&wgT,  g_wgT);

    const size_t sBN = (size_t)NN_ * HH_ * DD_;
    const size_t sBD = (size_t)NN_ * DD_;
    const size_t sNN = (size_t)NN_ * NN_;
    const int    HD  = HH_ * DD_;

    cudaFuncSetAttribute(k_flash, cudaFuncAttributeMaxDynamicSharedMemorySize, 163840);

    // 0) weight transposes
    {
        dim3 b(32, 8);
        k_transpose<<<dim3(32, 4), b>>>(Wq, wqT, DD_, HD);
        k_transpose<<<dim3(32, 4), b>>>(Wk, wkT, DD_, HD);
        k_transpose<<<dim3(32, 4), b>>>(Wv, wvT, DD_, HD);
        k_transpose<<<dim3(4, 32), b>>>(Wo, woT, HD, DD_);
        k_transpose<<<dim3(4, 4),  b>>>(Wg, wgT, DD_, DD_);
    }

    // 1) c = F_c + t_emb
    k_embed_add<<<BSZ * NN_, DD_>>>(F_c, t, c);

    // 2) QKV
    {
        dim3 g(8, 8, BSZ);
        gemm_tb<false, true, false><<<g, 256>>>(c, DD_, sBD, 0,
                                                wqT, DD_, 0, 0,
                                                q, HD, sBN, 0,
                                                bq, DD_, 1, 1.0f);
        gemm_tb<false, true, false><<<g, 256>>>(c, DD_, sBD, 0,
                                                wkT, DD_, 0, 0,
                                                k, HD, sBN, 0,
                                                bk, DD_, 1, 1.0f);
        gemm_tb<false, true, true><<<g, 256>>>(c, DD_, sBD, 0,
                                               wvT, DD_, 0, 0,
                                               vt, NN_, sBN, 0,
                                               bv, DD_, 1, 1.0f);
    }

    // 3) fused attention
    k_flash<<<dim3(8, BSZ * HH_), 256, 163840>>>(q, k, vt, ctx);

    // 4) h = ctx @ Wo + bo
    {
        dim3 g(1, 8, BSZ);
        gemm_tb<false, true, false><<<g, 256>>>(ctx, HD, sBN, 0,
                                                woT, HD, 0, 0,
                                                h, DD_, sBD, 0,
                                                bo, HD, 1, 1.0f);
    }
    // 5) hw = h @ Wg (transposed out)
    {
        dim3 g(1, 8, BSZ);
        gemm_tb<false, false, true><<<g, 256>>>(h, DD_, sBD, 0,
                                                wgT, DD_, 0, 0,
                                                hwt, NN_, sBD, 0,
                                                nullptr, DD_, 1, 1.0f);
    }
    // 6) feat = relu(A_t @ hw)
    {
        dim3 g(1, 8, BSZ);
        gemm_tb<true, false, false><<<g, 256>>>(A_t, NN_, sNN, 0,
                                                hwt, NN_, sBD, 0,
                                                feat, DD_, sBD, 0,
                                                nullptr, NN_, 1, 1.0f);
    }
    // 7) row normalize
    k_rownorm<<<BSZ * NN_, DD_>>>(feat, nrm);

    // 8) out = (norm @ norm^T) / 128
    {
        dim3 g(8, 8, BSZ);
        gemm_tb<false, false, false><<<g, 256>>>(nrm, DD_, sBD, 0,
                                                 nrm, DD_, sBD, 0,
                                                 out, NN_, sNN, 0,
                                                 nullptr, DD_, 1, 1.0f / 128.0f);
    }
}